// round 9
// baseline (speedup 1.0000x reference)
#include <cuda_runtime.h>
#include <cuda_bf16.h>
#include <cstdint>
#include <cstddef>

#define B_  4
#define L_  2048
#define D_  512
#define H_  8
#define DH_ 64

typedef __nv_bfloat16 bf16;

#define PROJ_E ((size_t)B_ * H_ * L_ * DH_)
__device__ bf16  g_qhi[PROJ_E];
__device__ bf16  g_qlo[PROJ_E];
__device__ bf16  g_khi[PROJ_E];
__device__ bf16  g_klo[PROJ_E];
__device__ bf16  g_vthi[PROJ_E];    // V transposed: [B,H,dh,L]
__device__ bf16  g_vtlo[PROJ_E];
__device__ float g_ctx[(size_t)B_ * L_ * D_];
__device__ float g_invl[(size_t)B_ * H_ * L_];
__device__ float g_attn_fb[(size_t)B_ * H_ * L_ * L_];

__device__ __forceinline__ uint32_t smem_u32(const void* p) {
    uint32_t a;
    asm("{ .reg .u64 t; cvta.to.shared.u64 t, %1; cvt.u32.u64 %0, t; }"
        : "=r"(a) : "l"(p));
    return a;
}

#define LDSM4(R0, R1, R2, R3, A) \
    asm volatile("ldmatrix.sync.aligned.m8n8.x4.shared.b16 {%0,%1,%2,%3}, [%4];" \
                 : "=r"(R0), "=r"(R1), "=r"(R2), "=r"(R3) : "r"(A))

#define MMA4(D, A0, A1, A2, A3, Bb0, Bb1) \
    asm volatile("mma.sync.aligned.m16n8k16.row.col.f32.bf16.bf16.f32 " \
                 "{%0,%1,%2,%3}, {%4,%5,%6,%7}, {%8,%9}, {%0,%1,%2,%3};" \
                 : "+f"((D)[0]), "+f"((D)[1]), "+f"((D)[2]), "+f"((D)[3]) \
                 : "r"(A0), "r"(A1), "r"(A2), "r"(A3), "r"(Bb0), "r"(Bb1))

#define CPA(dst, src) \
    asm volatile("cp.async.ca.shared.global [%0], [%1], 16;" \
                 :: "r"((uint32_t)(dst)), "l"(src) : "memory")
#define CPC() asm volatile("cp.async.commit_group;" ::: "memory")
#define CPW0() asm volatile("cp.async.wait_group 0;" ::: "memory")

__device__ __forceinline__ uint32_t pack2(bf16 a, bf16 b) {
    return (uint32_t)__bfloat16_as_ushort(a) |
           ((uint32_t)__bfloat16_as_ushort(b) << 16);
}

// =====================================================================
// GEMM body (device fn): C[r,c] = sum_k X[r,k]*W[c,k] + bias[c]
// mode 0: fp32 flat; mode 1: bf16 hi/lo [B,H,L,64]; mode 2: [B,H,64,L]
// 128x128 tile, 256 threads, register-prefetch pipelined.
// =====================================================================
#define GP 144
#define G_XHI 0
#define G_XLO 18432
#define G_WHI 36864
#define G_WLO 55296
#define G_SM_TOTAL 73728
// mode-2 transpose staging (reuses same smem after MMAs)
// NOTE: pitch must be a multiple of 16 for uint4 smem reads.
#define T_PT  272
#define T_HI  0
#define T_LO  36864

__device__ __forceinline__ void
gemm_body(const float* __restrict__ X, const float* __restrict__ W,
          const float* __restrict__ bias,
          float* __restrict__ out32, bf16* __restrict__ oHi,
          bf16* __restrict__ oLo, int mode, int n0, int mb,
          char* sm_, uint32_t sb)
{
    const int t = threadIdx.x, lane = t & 31, w = t >> 5, qq = lane & 3;
    const int m0 = w * 16;
    const int rB = (lane & 7) + ((lane & 16) >> 1);
    const int cB = (lane >> 3) & 1;
    const int rA = lane & 15, cA = lane >> 4;

    float S[16][4];
#pragma unroll
    for (int i = 0; i < 16; i++)
#pragma unroll
        for (int j = 0; j < 4; j++) S[i][j] = 0.f;

    float4 xr[8], wr[8];
#define LOADCHUNK(kc_)                                                        \
    do {                                                                      \
        _Pragma("unroll")                                                     \
        for (int e = 0; e < 8; e++) {                                         \
            int i = t + e * 256;                                              \
            int row = i >> 4, c4 = (i & 15) * 4;                              \
            xr[e] = *(const float4*)(X + (size_t)(mb + row) * D_ + (kc_) + c4);\
            wr[e] = *(const float4*)(W + (size_t)(n0 + row) * D_ + (kc_) + c4);\
        }                                                                     \
    } while (0)

    LOADCHUNK(0);

#pragma unroll 1
    for (int kc6 = 0; kc6 < 8; kc6++) {
        __syncthreads();
#pragma unroll
        for (int e = 0; e < 8; e++) {
            int i = t + e * 256;
            int row = i >> 4, c4 = (i & 15) * 4;
            float4 x = xr[e];
            bf16 h0 = __float2bfloat16(x.x), h1 = __float2bfloat16(x.y);
            bf16 h2 = __float2bfloat16(x.z), h3 = __float2bfloat16(x.w);
            *(uint2*)(sm_ + G_XHI + row * GP + c4 * 2) =
                make_uint2(pack2(h0, h1), pack2(h2, h3));
            *(uint2*)(sm_ + G_XLO + row * GP + c4 * 2) = make_uint2(
                pack2(__float2bfloat16(x.x - __bfloat162float(h0)),
                      __float2bfloat16(x.y - __bfloat162float(h1))),
                pack2(__float2bfloat16(x.z - __bfloat162float(h2)),
                      __float2bfloat16(x.w - __bfloat162float(h3))));
            float4 wv = wr[e];
            h0 = __float2bfloat16(wv.x); h1 = __float2bfloat16(wv.y);
            h2 = __float2bfloat16(wv.z); h3 = __float2bfloat16(wv.w);
            *(uint2*)(sm_ + G_WHI + row * GP + c4 * 2) =
                make_uint2(pack2(h0, h1), pack2(h2, h3));
            *(uint2*)(sm_ + G_WLO + row * GP + c4 * 2) = make_uint2(
                pack2(__float2bfloat16(wv.x - __bfloat162float(h0)),
                      __float2bfloat16(wv.y - __bfloat162float(h1))),
                pack2(__float2bfloat16(wv.z - __bfloat162float(h2)),
                      __float2bfloat16(wv.w - __bfloat162float(h3))));
        }
        __syncthreads();
        if (kc6 < 7) LOADCHUNK((kc6 + 1) * 64);

#pragma unroll
        for (int ks = 0; ks < 4; ks++) {
            uint32_t ah0, ah1, ah2, ah3, al0, al1, al2, al3;
            LDSM4(ah0, ah1, ah2, ah3,
                  sb + G_XHI + (m0 + rA) * GP + ks * 32 + cA * 16);
            LDSM4(al0, al1, al2, al3,
                  sb + G_XLO + (m0 + rA) * GP + ks * 32 + cA * 16);
#pragma unroll
            for (int n2 = 0; n2 < 8; n2++) {
                uint32_t b0, b1, b2, b3;
                uint32_t ad = sb + G_WHI + (n2 * 16 + rB) * GP + ks * 32 + cB * 16;
                LDSM4(b0, b1, b2, b3, ad);
                MMA4(S[2 * n2],     ah0, ah1, ah2, ah3, b0, b1);
                MMA4(S[2 * n2 + 1], ah0, ah1, ah2, ah3, b2, b3);
                MMA4(S[2 * n2],     al0, al1, al2, al3, b0, b1);
                MMA4(S[2 * n2 + 1], al0, al1, al2, al3, b2, b3);
                LDSM4(b0, b1, b2, b3, ad + (G_WLO - G_WHI));
                MMA4(S[2 * n2],     ah0, ah1, ah2, ah3, b0, b1);
                MMA4(S[2 * n2 + 1], ah0, ah1, ah2, ah3, b2, b3);
            }
        }
    }
#undef LOADCHUNK

    const int rA_ = mb + m0 + (lane >> 2);
    const int rB_ = rA_ + 8;

    if (mode == 2) {
        // stage transposed bf16 hi/lo tile in smem, then coalesced write
        __syncthreads();
        const int mA = m0 + (lane >> 2), mB = mA + 8;
#pragma unroll
        for (int nt = 0; nt < 16; nt++) {
            int c = nt * 8 + qq * 2;        // local col 0..126
            float bs0 = bias[n0 + c], bs1 = bias[n0 + c + 1];
            float v00 = S[nt][0] + bs0, v01 = S[nt][1] + bs1;
            float v10 = S[nt][2] + bs0, v11 = S[nt][3] + bs1;
            bf16 h;
            h = __float2bfloat16(v00);
            *(bf16*)(sm_ + T_HI + c * T_PT + mA * 2) = h;
            *(bf16*)(sm_ + T_LO + c * T_PT + mA * 2) =
                __float2bfloat16(v00 - __bfloat162float(h));
            h = __float2bfloat16(v01);
            *(bf16*)(sm_ + T_HI + (c + 1) * T_PT + mA * 2) = h;
            *(bf16*)(sm_ + T_LO + (c + 1) * T_PT + mA * 2) =
                __float2bfloat16(v01 - __bfloat162float(h));
            h = __float2bfloat16(v10);
            *(bf16*)(sm_ + T_HI + c * T_PT + mB * 2) = h;
            *(bf16*)(sm_ + T_LO + c * T_PT + mB * 2) =
                __float2bfloat16(v10 - __bfloat162float(h));
            h = __float2bfloat16(v11);
            *(bf16*)(sm_ + T_HI + (c + 1) * T_PT + mB * 2) = h;
            *(bf16*)(sm_ + T_LO + (c + 1) * T_PT + mB * 2) =
                __float2bfloat16(v11 - __bfloat162float(h));
        }
        __syncthreads();
        // write: each dh-row is 128 contiguous bf16 in [B,H,dh,L]
        const int bA = mb >> 11, lA0 = mb & 2047;
        const int cl = t >> 1, half = t & 1;    // 128 rows x 2 halves
        const int hh = (n0 + cl) >> 6, dh = (n0 + cl) & 63;
        size_t gbase = ((size_t)((bA * H_ + hh) * DH_) + dh) * L_ + lA0 + half * 64;
        const char* srcH = sm_ + T_HI + cl * T_PT + half * 128;
        const char* srcL = sm_ + T_LO + cl * T_PT + half * 128;
#pragma unroll
        for (int e = 0; e < 8; e++) {
            *(uint4*)(oHi + gbase + e * 8) = *(const uint4*)(srcH + e * 16);
            *(uint4*)(oLo + gbase + e * 8) = *(const uint4*)(srcL + e * 16);
        }
        return;
    }

#pragma unroll
    for (int nt = 0; nt < 16; nt++) {
        int c = n0 + nt * 8 + qq * 2;
        float bs0 = bias[c], bs1 = bias[c + 1];
        float v00 = S[nt][0] + bs0, v01 = S[nt][1] + bs1;
        float v10 = S[nt][2] + bs0, v11 = S[nt][3] + bs1;
        if (mode == 0) {
            *(float2*)(out32 + (size_t)rA_ * D_ + c) = make_float2(v00, v01);
            *(float2*)(out32 + (size_t)rB_ * D_ + c) = make_float2(v10, v11);
        } else {
            int hh = c >> 6, dh = c & 63;
            int bA = rA_ >> 11, lA = rA_ & 2047;
            int bB = rB_ >> 11, lB = rB_ & 2047;
            size_t iA = ((size_t)((bA * H_ + hh) * L_) + lA) * DH_ + dh;
            size_t iB = ((size_t)((bB * H_ + hh) * L_) + lB) * DH_ + dh;
            bf16 h0 = __float2bfloat16(v00), h1 = __float2bfloat16(v01);
            *(uint32_t*)(oHi + iA) = pack2(h0, h1);
            *(uint32_t*)(oLo + iA) = pack2(
                __float2bfloat16(v00 - __bfloat162float(h0)),
                __float2bfloat16(v01 - __bfloat162float(h1)));
            h0 = __float2bfloat16(v10); h1 = __float2bfloat16(v11);
            *(uint32_t*)(oHi + iB) = pack2(h0, h1);
            *(uint32_t*)(oLo + iB) = pack2(
                __float2bfloat16(v10 - __bfloat162float(h0)),
                __float2bfloat16(v11 - __bfloat162float(h1)));
        }
    }
}

// ---- fused QKV projections: grid.x = 768, z interleaved ----
__global__ void __launch_bounds__(256, 1)
qkv_proj(const float* __restrict__ q, const float* __restrict__ k,
         const float* __restrict__ v,
         const float* __restrict__ wq, const float* __restrict__ bq,
         const float* __restrict__ wk, const float* __restrict__ bk,
         const float* __restrict__ wv, const float* __restrict__ bv,
         bf16* qhi, bf16* qlo, bf16* khi, bf16* klo,
         bf16* vthi, bf16* vtlo)
{
    extern __shared__ char sm_[];
    const uint32_t sb = smem_u32(sm_);
    const int bx = blockIdx.x;
    const int z = bx % 3, inner = bx / 3;
    const int n0 = (inner & 3) * 128, mb = (inner >> 2) * 128;
    if (z == 0)
        gemm_body(q, wq, bq, nullptr, qhi, qlo, 1, n0, mb, sm_, sb);
    else if (z == 1)
        gemm_body(k, wk, bk, nullptr, khi, klo, 1, n0, mb, sm_, sb);
    else
        gemm_body(v, wv, bv, nullptr, vthi, vtlo, 2, n0, mb, sm_, sb);
}

// ---- fused out-GEMM + attn normalization: grid.x = 1024 ----
__global__ void __launch_bounds__(256, 1)
out_scale(const float* __restrict__ ctx, const float* __restrict__ wo,
          const float* __restrict__ bo, float* __restrict__ out,
          float4* __restrict__ attn4, const float* __restrict__ invl)
{
    extern __shared__ char sm_[];
    const int bx = blockIdx.x;
    if ((bx & 3) == 0) {
        const uint32_t sb = smem_u32(sm_);
        int idx = bx >> 2;                       // 0..255
        gemm_body(ctx, wo, bo, out, nullptr, nullptr, 0,
                  (idx & 3) * 128, (idx >> 2) * 128, sm_, sb);
    } else {
        const size_t n4 = (size_t)B_ * H_ * L_ * L_ / 4;
        int sidx = bx - ((bx + 3) >> 2);         // 0..767
        size_t i = (size_t)sidx * 256 + threadIdx.x;
        const size_t stride = (size_t)768 * 256;
        for (; i < n4; i += stride) {
            float s = __ldg(invl + (i >> 9));
            float4 vv = attn4[i];
            vv.x *= s; vv.y *= s; vv.z *= s; vv.w *= s;
            attn4[i] = vv;
        }
    }
}

// =====================================================================
// Fused attention (unchanged math), occupancy 3 CTAs/SM.
// =====================================================================
#define PK 144
#define F_M0   0
#define F_M1   256
#define F_KHI0 1024
#define F_KLO0 (F_KHI0 + 9216)
#define F_KHI1 (F_KLO0 + 9216)
#define F_KLO1 (F_KHI1 + 9216)
#define F_VHI0 (F_KLO1 + 9216)
#define F_VLO0 (F_VHI0 + 9216)
#define F_VHI1 (F_VLO0 + 9216)
#define F_VLO1 (F_VHI1 + 9216)
#define F_TOTAL (F_VLO1 + 9216)   // 74752

__global__ void __launch_bounds__(128, 3)
attn_fused(const bf16* __restrict__ qhi, const bf16* __restrict__ qlo,
           const bf16* __restrict__ khi, const bf16* __restrict__ klo,
           const bf16* __restrict__ vthi, const bf16* __restrict__ vtlo,
           const int*  __restrict__ mask,
           float* __restrict__ attn, float* __restrict__ ctx,
           float* __restrict__ invl_out)
{
    extern __shared__ char sm_[];
    const uint32_t sb = smem_u32(sm_);
    const int t = threadIdx.x, lane = t & 31, w = t >> 5, qq = lane & 3;
    const int q0 = blockIdx.x * 64, h = blockIdx.y, b = blockIdx.z;
    const size_t hb = (size_t)(b * H_ + h) * L_;
    const size_t headoff = hb * DH_;
    const int m0 = w * 16;
    const int rB = (lane & 7) + ((lane & 16) >> 1);
    const int cB = (lane >> 3) & 1;
    const int rA = lane & 15, cA = lane >> 4;
    const int r0 = m0 + (lane >> 2);

#pragma unroll
    for (int e = 0; e < 4; e++) {
        int i = t + e * 128;
        int row = i >> 3, c16 = i & 7;
        *(uint4*)(sm_ + F_KHI0 + row * PK + c16 * 16) =
            *(const uint4*)(qhi + headoff + (size_t)(q0 + row) * DH_ + c16 * 8);
        *(uint4*)(sm_ + F_KLO0 + row * PK + c16 * 16) =
            *(const uint4*)(qlo + headoff + (size_t)(q0 + row) * DH_ + c16 * 8);
    }
    __syncthreads();
    uint32_t qh[4][4], ql[4][4];
#pragma unroll
    for (int ks = 0; ks < 4; ks++) {
        LDSM4(qh[ks][0], qh[ks][1], qh[ks][2], qh[ks][3],
              sb + F_KHI0 + (m0 + rA) * PK + ks * 32 + cA * 16);
        LDSM4(ql[ks][0], ql[ks][1], ql[ks][2], ql[ks][3],
              sb + F_KLO0 + (m0 + rA) * PK + ks * 32 + cA * 16);
    }
    __syncthreads();

#define PREFETCH(kt_, par_)                                                   \
    do {                                                                      \
        uint32_t kh_ = sb + ((par_) ? F_KHI1 : F_KHI0);                       \
        uint32_t vh_ = sb + ((par_) ? F_VHI1 : F_VHI0);                       \
        const bf16* kg = khi + headoff + (size_t)((kt_) * 64) * DH_;          \
        const bf16* lg = klo + headoff + (size_t)((kt_) * 64) * DH_;          \
        const bf16* vg = vthi + headoff + (kt_) * 64;                         \
        const bf16* wg = vtlo + headoff + (kt_) * 64;                         \
        _Pragma("unroll")                                                     \
        for (int e = 0; e < 4; e++) {                                         \
            int i = t + e * 128;                                              \
            int row = i >> 3, c16 = i & 7;                                    \
            CPA(kh_ + row * PK + c16 * 16, kg + (size_t)row * DH_ + c16 * 8); \
            CPA(kh_ + 9216 + row * PK + c16 * 16,                             \
                lg + (size_t)row * DH_ + c16 * 8);                            \
            CPA(vh_ + row * PK + c16 * 16, vg + (size_t)row * L_ + c16 * 8);  \
            CPA(vh_ + 9216 + row * PK + c16 * 16,                             \
                wg + (size_t)row * L_ + c16 * 8);                             \
        }                                                                     \
        if (t < 16)                                                           \
            CPA(sb + ((par_) ? F_M1 : F_M0) + t * 16,                         \
                mask + b * L_ + (kt_) * 64 + t * 4);                          \
        CPC();                                                                \
    } while (0)

    PREFETCH(0, 0);

    float O[8][4];
#pragma unroll
    for (int i = 0; i < 8; i++)
#pragma unroll
        for (int j = 0; j < 4; j++) O[i][j] = 0.f;
    float lrunA = 0.f, lrunB = 0.f;

#pragma unroll 1
    for (int kt6 = 0; kt6 < 32; kt6++) {
        const int par = kt6 & 1;
        CPW0();
        __syncthreads();
        if (kt6 < 31) PREFETCH(kt6 + 1, par ^ 1);

        const uint32_t khb = sb + (par ? F_KHI1 : F_KHI0);
        const uint32_t vhb = sb + (par ? F_VHI1 : F_VHI0);
        const int* mi = (const int*)(sm_ + (par ? F_M1 : F_M0));

        float S[8][4];
#pragma unroll
        for (int i = 0; i < 8; i++)
#pragma unroll
            for (int j = 0; j < 4; j++) S[i][j] = 0.f;

#pragma unroll
        for (int ks = 0; ks < 4; ks++) {
#pragma unroll
            for (int n2 = 0; n2 < 4; n2++) {
                uint32_t b0, b1, b2, b3;
                uint32_t ad = khb + (n2 * 16 + rB) * PK + ks * 32 + cB * 16;
                LDSM4(b0, b1, b2, b3, ad);
                MMA4(S[2 * n2],     qh[ks][0], qh[ks][1], qh[ks][2], qh[ks][3], b0, b1);
                MMA4(S[2 * n2 + 1], qh[ks][0], qh[ks][1], qh[ks][2], qh[ks][3], b2, b3);
                MMA4(S[2 * n2],     ql[ks][0], ql[ks][1], ql[ks][2], ql[ks][3], b0, b1);
                MMA4(S[2 * n2 + 1], ql[ks][0], ql[ks][1], ql[ks][2], ql[ks][3], b2, b3);
                LDSM4(b0, b1, b2, b3, ad + 9216);
                MMA4(S[2 * n2],     qh[ks][0], qh[ks][1], qh[ks][2], qh[ks][3], b0, b1);
                MMA4(S[2 * n2 + 1], qh[ks][0], qh[ks][1], qh[ks][2], qh[ks][3], b2, b3);
            }
        }

        float* arow0 = attn + (hb + q0 + r0) * (size_t)L_ + kt6 * 64;
        float* arow1 = arow0 + 8 * L_;
#pragma unroll
        for (int nt = 0; nt < 8; nt++) {
            int c0 = nt * 8 + qq * 2;
            bool k0m = mi[c0] != 0, k1m = mi[c0 + 1] != 0;
            float e0 = k0m ? 0.f : __expf(S[nt][0] * 0.125f);
            float e1 = k1m ? 0.f : __expf(S[nt][1] * 0.125f);
            float e2 = k0m ? 0.f : __expf(S[nt][2] * 0.125f);
            float e3 = k1m ? 0.f : __expf(S[nt][3] * 0.125f);
            lrunA += e0 + e1; lrunB += e2 + e3;
            S[nt][0] = e0; S[nt][1] = e1; S[nt][2] = e2; S[nt][3] = e3;
            *(float2*)(arow0 + c0) = make_float2(e0, e1);
            *(float2*)(arow1 + c0) = make_float2(e2, e3);
        }

#pragma unroll
        for (int ks = 0; ks < 4; ks++) {
            bf16 h00 = __float2bfloat16(S[2 * ks][0]);
            bf16 h01 = __float2bfloat16(S[2 * ks][1]);
            bf16 h02 = __float2bfloat16(S[2 * ks][2]);
            bf16 h03 = __float2bfloat16(S[2 * ks][3]);
            bf16 h10 = __float2bfloat16(S[2 * ks + 1][0]);
            bf16 h11 = __float2bfloat16(S[2 * ks + 1][1]);
            bf16 h12 = __float2bfloat16(S[2 * ks + 1][2]);
            bf16 h13 = __float2bfloat16(S[2 * ks + 1][3]);
            uint32_t a0h = pack2(h00, h01), a1h = pack2(h02, h03);
            uint32_t a2h = pack2(h10, h11), a3h = pack2(h12, h13);
            uint32_t a0l = pack2(
                __float2bfloat16(S[2 * ks][0] - __bfloat162float(h00)),
                __float2bfloat16(S[2 * ks][1] - __bfloat162float(h01)));
            uint32_t a1l = pack2(
                __float2bfloat16(S[2 * ks][2] - __bfloat162float(h02)),
                __float2bfloat16(S[2 * ks][3] - __bfloat162float(h03)));
            uint32_t a2l = pack2(
                __float2bfloat16(S[2 * ks + 1][0] - __bfloat162float(h10)),
                __float2bfloat16(S[2 * ks + 1][1] - __bfloat162float(h11)));
            uint32_t a3l = pack2(
                __float2bfloat16(S[2 * ks + 1][2] - __bfloat162float(h12)),
                __float2bfloat16(S[2 * ks + 1][3] - __bfloat162float(h13)));
#pragma unroll
            for (int n2 = 0; n2 < 4; n2++) {
                uint32_t b0, b1, b2, b3;
                uint32_t ad = vhb + (n2 * 16 + rB) * PK + ks * 32 + cB * 16;
                LDSM4(b0, b1, b2, b3, ad);
                MMA4(O[2 * n2],     a0h, a1h, a2h, a3h, b0, b1);
                MMA4(O[2 * n2 + 1], a0h, a1h, a2h, a3h, b2, b3);
                MMA4(O[2 * n2],     a0l, a1l, a2l, a3l, b0, b1);
                MMA4(O[2 * n2 + 1], a0l, a1l, a2l, a3l, b2, b3);
                LDSM4(b0, b1, b2, b3, ad + 9216);
                MMA4(O[2 * n2],     a0h, a1h, a2h, a3h, b0, b1);
                MMA4(O[2 * n2 + 1], a0h, a1h, a2h, a3h, b2, b3);
            }
        }
        __syncthreads();
    }
#undef PREFETCH

    lrunA += __shfl_xor_sync(0xffffffffu, lrunA, 1);
    lrunA += __shfl_xor_sync(0xffffffffu, lrunA, 2);
    lrunB += __shfl_xor_sync(0xffffffffu, lrunB, 1);
    lrunB += __shfl_xor_sync(0xffffffffu, lrunB, 2);
    float ilA = 1.f / lrunA, ilB = 1.f / lrunB;
    if (qq == 0) {
        invl_out[hb + q0 + r0]     = ilA;
        invl_out[hb + q0 + r0 + 8] = ilB;
    }
    int rg = q0 + r0;
#pragma unroll
    for (int nt = 0; nt < 8; nt++) {
        int d = nt * 8 + qq * 2;
        *(float2*)(ctx + ((size_t)b * L_ + rg) * D_ + h * 64 + d) =
            make_float2(O[nt][0] * ilA, O[nt][1] * ilA);
        *(float2*)(ctx + ((size_t)b * L_ + rg + 8) * D_ + h * 64 + d) =
            make_float2(O[nt][2] * ilB, O[nt][3] * ilB);
    }
}

extern "C" void kernel_launch(void* const* d_in, const int* in_sizes, int n_in,
                              void* d_out, int out_size)
{
    const float* q    = (const float*)d_in[0];
    const float* k    = (const float*)d_in[1];
    const float* v    = (const float*)d_in[2];
    const int*   mask = (const int*)  d_in[3];
    const float* wq_w = (const float*)d_in[4];
    const float* wq_b = (const float*)d_in[5];
    const float* wk_w = (const float*)d_in[6];
    const float* wk_b = (const float*)d_in[7];
    const float* wv_w = (const float*)d_in[8];
    const float* wv_b = (const float*)d_in[9];
    const float* wo_w = (const float*)d_in[10];
    const float* wo_b = (const float*)d_in[11];

    float* out = (float*)d_out;
    const long long OUT_E  = (long long)B_ * L_ * D_;
    const long long ATTN_E = (long long)B_ * H_ * L_ * L_;

    float* attn_ptr;
    if ((long long)out_size >= OUT_E + ATTN_E) {
        attn_ptr = out + OUT_E;
    } else {
        void* p = nullptr;
        cudaGetSymbolAddress(&p, g_attn_fb);
        attn_ptr = (float*)p;
    }

    bf16 *qhi, *qlo, *khi, *klo, *vthi, *vtlo;
    float *ctx, *invl;
    { void* p; cudaGetSymbolAddress(&p, g_qhi);  qhi  = (bf16*)p; }
    { void* p; cudaGetSymbolAddress(&p, g_qlo);  qlo  = (bf16*)p; }
    { void* p; cudaGetSymbolAddress(&p, g_khi);  khi  = (bf16*)p; }
    { void* p; cudaGetSymbolAddress(&p, g_klo);  klo  = (bf16*)p; }
    { void* p; cudaGetSymbolAddress(&p, g_vthi); vthi = (bf16*)p; }
    { void* p; cudaGetSymbolAddress(&p, g_vtlo); vtlo = (bf16*)p; }
    { void* p; cudaGetSymbolAddress(&p, g_ctx);  ctx  = (float*)p; }
    { void* p; cudaGetSymbolAddress(&p, g_invl); invl = (float*)p; }

    cudaFuncSetAttribute(qkv_proj,
        cudaFuncAttributeMaxDynamicSharedMemorySize, G_SM_TOTAL);
    cudaFuncSetAttribute(out_scale,
        cudaFuncAttributeMaxDynamicSharedMemorySize, G_SM_TOTAL);
    cudaFuncSetAttribute(attn_fused,
        cudaFuncAttributeMaxDynamicSharedMemorySize, F_TOTAL);

    qkv_proj<<<768, 256, G_SM_TOTAL>>>(q, k, v, wq_w, wq_b, wk_w, wk_b,
                                       wv_w, wv_b, qhi, qlo, khi, klo,
                                       vthi, vtlo);

    dim3 grid_attn(L_ / 64, H_, B_);             // (32, 8, 4)
    attn_fused<<<grid_attn, 128, F_TOTAL>>>(qhi, qlo, khi, klo, vthi, vtlo,
                                            mask, attn_ptr, ctx, invl);

    out_scale<<<1024, 256, G_SM_TOTAL>>>(ctx, wo_w, wo_b, out,
                                         (float4*)attn_ptr, invl);
}

// round 10
// speedup vs baseline: 1.4899x; 1.4899x over previous
#include <cuda_runtime.h>
#include <cuda_bf16.h>
#include <cstdint>
#include <cstddef>

#define B_  4
#define L_  2048
#define D_  512
#define H_  8
#define DH_ 64

typedef __nv_bfloat16 bf16;

#define PROJ_E ((size_t)B_ * H_ * L_ * DH_)
__device__ bf16  g_qhi[PROJ_E];
__device__ bf16  g_qlo[PROJ_E];
__device__ bf16  g_khi[PROJ_E];
__device__ bf16  g_klo[PROJ_E];
__device__ bf16  g_vthi[PROJ_E];    // V transposed: [B,H,dh,L]
__device__ bf16  g_vtlo[PROJ_E];
__device__ float g_ctx[(size_t)B_ * L_ * D_];
__device__ float g_invl[(size_t)B_ * H_ * L_];
__device__ float g_attn_fb[(size_t)B_ * H_ * L_ * L_];

__device__ __forceinline__ uint32_t smem_u32(const void* p) {
    uint32_t a;
    asm("{ .reg .u64 t; cvta.to.shared.u64 t, %1; cvt.u32.u64 %0, t; }"
        : "=r"(a) : "l"(p));
    return a;
}

#define LDSM4(R0, R1, R2, R3, A) \
    asm volatile("ldmatrix.sync.aligned.m8n8.x4.shared.b16 {%0,%1,%2,%3}, [%4];" \
                 : "=r"(R0), "=r"(R1), "=r"(R2), "=r"(R3) : "r"(A))

#define MMA4(D, A0, A1, A2, A3, Bb0, Bb1) \
    asm volatile("mma.sync.aligned.m16n8k16.row.col.f32.bf16.bf16.f32 " \
                 "{%0,%1,%2,%3}, {%4,%5,%6,%7}, {%8,%9}, {%0,%1,%2,%3};" \
                 : "+f"((D)[0]), "+f"((D)[1]), "+f"((D)[2]), "+f"((D)[3]) \
                 : "r"(A0), "r"(A1), "r"(A2), "r"(A3), "r"(Bb0), "r"(Bb1))

#define CPA(dst, src) \
    asm volatile("cp.async.ca.shared.global [%0], [%1], 16;" \
                 :: "r"((uint32_t)(dst)), "l"(src) : "memory")
#define CPC()  asm volatile("cp.async.commit_group;" ::: "memory")
#define CPW0() asm volatile("cp.async.wait_group 0;" ::: "memory")
#define CPW1() asm volatile("cp.async.wait_group 1;" ::: "memory")

__device__ __forceinline__ uint32_t pack2(bf16 a, bf16 b) {
    return (uint32_t)__bfloat16_as_ushort(a) |
           ((uint32_t)__bfloat16_as_ushort(b) << 16);
}

// =====================================================================
// GEMM via mma.sync, register-prefetch pipelined (R7 baseline).
// mode 0: fp32 flat; mode 1: bf16 hi/lo [B,H,L,64]; mode 2: [B,H,64,L]
// =====================================================================
#define GP 144
#define G_XHI 0
#define G_XLO 18432
#define G_WHI 36864
#define G_WLO 55296
#define G_SM_TOTAL 73728
// mode-2 transpose staging (reuses same smem after MMAs); pitch mult of 16
#define T_PT  272
#define T_HI  0
#define T_LO  36864

__global__ void __launch_bounds__(256, 1)
gemm_mma(const float* __restrict__ X, const float* __restrict__ W,
         const float* __restrict__ bias,
         float* __restrict__ out32, bf16* __restrict__ oHi,
         bf16* __restrict__ oLo, int mode)
{
    extern __shared__ char sm_[];
    const uint32_t sb = smem_u32(sm_);
    const int t = threadIdx.x, lane = t & 31, w = t >> 5, qq = lane & 3;
    const int n0 = blockIdx.x * 128, mb = blockIdx.y * 128;
    const int m0 = w * 16;
    const int rB = (lane & 7) + ((lane & 16) >> 1);
    const int cB = (lane >> 3) & 1;
    const int rA = lane & 15, cA = lane >> 4;

    float S[16][4];
#pragma unroll
    for (int i = 0; i < 16; i++)
#pragma unroll
        for (int j = 0; j < 4; j++) S[i][j] = 0.f;

    float4 xr[8], wr[8];
#define LOADCHUNK(kc_)                                                        \
    do {                                                                      \
        _Pragma("unroll")                                                     \
        for (int e = 0; e < 8; e++) {                                         \
            int i = t + e * 256;                                              \
            int row = i >> 4, c4 = (i & 15) * 4;                              \
            xr[e] = *(const float4*)(X + (size_t)(mb + row) * D_ + (kc_) + c4);\
            wr[e] = *(const float4*)(W + (size_t)(n0 + row) * D_ + (kc_) + c4);\
        }                                                                     \
    } while (0)

    LOADCHUNK(0);

#pragma unroll 1
    for (int kc6 = 0; kc6 < 8; kc6++) {
        __syncthreads();
#pragma unroll
        for (int e = 0; e < 8; e++) {
            int i = t + e * 256;
            int row = i >> 4, c4 = (i & 15) * 4;
            float4 x = xr[e];
            bf16 h0 = __float2bfloat16(x.x), h1 = __float2bfloat16(x.y);
            bf16 h2 = __float2bfloat16(x.z), h3 = __float2bfloat16(x.w);
            *(uint2*)(sm_ + G_XHI + row * GP + c4 * 2) =
                make_uint2(pack2(h0, h1), pack2(h2, h3));
            *(uint2*)(sm_ + G_XLO + row * GP + c4 * 2) = make_uint2(
                pack2(__float2bfloat16(x.x - __bfloat162float(h0)),
                      __float2bfloat16(x.y - __bfloat162float(h1))),
                pack2(__float2bfloat16(x.z - __bfloat162float(h2)),
                      __float2bfloat16(x.w - __bfloat162float(h3))));
            float4 wv = wr[e];
            h0 = __float2bfloat16(wv.x); h1 = __float2bfloat16(wv.y);
            h2 = __float2bfloat16(wv.z); h3 = __float2bfloat16(wv.w);
            *(uint2*)(sm_ + G_WHI + row * GP + c4 * 2) =
                make_uint2(pack2(h0, h1), pack2(h2, h3));
            *(uint2*)(sm_ + G_WLO + row * GP + c4 * 2) = make_uint2(
                pack2(__float2bfloat16(wv.x - __bfloat162float(h0)),
                      __float2bfloat16(wv.y - __bfloat162float(h1))),
                pack2(__float2bfloat16(wv.z - __bfloat162float(h2)),
                      __float2bfloat16(wv.w - __bfloat162float(h3))));
        }
        __syncthreads();
        if (kc6 < 7) LOADCHUNK((kc6 + 1) * 64);

#pragma unroll
        for (int ks = 0; ks < 4; ks++) {
            uint32_t ah0, ah1, ah2, ah3, al0, al1, al2, al3;
            LDSM4(ah0, ah1, ah2, ah3,
                  sb + G_XHI + (m0 + rA) * GP + ks * 32 + cA * 16);
            LDSM4(al0, al1, al2, al3,
                  sb + G_XLO + (m0 + rA) * GP + ks * 32 + cA * 16);
#pragma unroll
            for (int n2 = 0; n2 < 8; n2++) {
                uint32_t b0, b1, b2, b3;
                uint32_t ad = sb + G_WHI + (n2 * 16 + rB) * GP + ks * 32 + cB * 16;
                LDSM4(b0, b1, b2, b3, ad);
                MMA4(S[2 * n2],     ah0, ah1, ah2, ah3, b0, b1);
                MMA4(S[2 * n2 + 1], ah0, ah1, ah2, ah3, b2, b3);
                MMA4(S[2 * n2],     al0, al1, al2, al3, b0, b1);
                MMA4(S[2 * n2 + 1], al0, al1, al2, al3, b2, b3);
                LDSM4(b0, b1, b2, b3, ad + (G_WLO - G_WHI));
                MMA4(S[2 * n2],     ah0, ah1, ah2, ah3, b0, b1);
                MMA4(S[2 * n2 + 1], ah0, ah1, ah2, ah3, b2, b3);
            }
        }
    }
#undef LOADCHUNK

    const int rA_ = mb + m0 + (lane >> 2);
    const int rB_ = rA_ + 8;

    if (mode == 2) {
        // stage transposed bf16 hi/lo tile in smem, then coalesced write
        __syncthreads();
        const int mA = m0 + (lane >> 2), mB = mA + 8;
#pragma unroll
        for (int nt = 0; nt < 16; nt++) {
            int c = nt * 8 + qq * 2;
            float bs0 = bias[n0 + c], bs1 = bias[n0 + c + 1];
            float v00 = S[nt][0] + bs0, v01 = S[nt][1] + bs1;
            float v10 = S[nt][2] + bs0, v11 = S[nt][3] + bs1;
            bf16 h;
            h = __float2bfloat16(v00);
            *(bf16*)(sm_ + T_HI + c * T_PT + mA * 2) = h;
            *(bf16*)(sm_ + T_LO + c * T_PT + mA * 2) =
                __float2bfloat16(v00 - __bfloat162float(h));
            h = __float2bfloat16(v01);
            *(bf16*)(sm_ + T_HI + (c + 1) * T_PT + mA * 2) = h;
            *(bf16*)(sm_ + T_LO + (c + 1) * T_PT + mA * 2) =
                __float2bfloat16(v01 - __bfloat162float(h));
            h = __float2bfloat16(v10);
            *(bf16*)(sm_ + T_HI + c * T_PT + mB * 2) = h;
            *(bf16*)(sm_ + T_LO + c * T_PT + mB * 2) =
                __float2bfloat16(v10 - __bfloat162float(h));
            h = __float2bfloat16(v11);
            *(bf16*)(sm_ + T_HI + (c + 1) * T_PT + mB * 2) = h;
            *(bf16*)(sm_ + T_LO + (c + 1) * T_PT + mB * 2) =
                __float2bfloat16(v11 - __bfloat162float(h));
        }
        __syncthreads();
        const int bA = mb >> 11, lA0 = mb & 2047;
        const int cl = t >> 1, half = t & 1;
        const int hh = (n0 + cl) >> 6, dh = (n0 + cl) & 63;
        size_t gbase = ((size_t)((bA * H_ + hh) * DH_) + dh) * L_ + lA0 + half * 64;
        const char* srcH = sm_ + T_HI + cl * T_PT + half * 128;
        const char* srcL = sm_ + T_LO + cl * T_PT + half * 128;
#pragma unroll
        for (int e = 0; e < 8; e++) {
            *(uint4*)(oHi + gbase + e * 8) = *(const uint4*)(srcH + e * 16);
            *(uint4*)(oLo + gbase + e * 8) = *(const uint4*)(srcL + e * 16);
        }
        return;
    }

#pragma unroll
    for (int nt = 0; nt < 16; nt++) {
        int c = n0 + nt * 8 + qq * 2;
        float bs0 = bias[c], bs1 = bias[c + 1];
        float v00 = S[nt][0] + bs0, v01 = S[nt][1] + bs1;
        float v10 = S[nt][2] + bs0, v11 = S[nt][3] + bs1;
        if (mode == 0) {
            *(float2*)(out32 + (size_t)rA_ * D_ + c) = make_float2(v00, v01);
            *(float2*)(out32 + (size_t)rB_ * D_ + c) = make_float2(v10, v11);
        } else {
            int hh = c >> 6, dh = c & 63;
            int bA = rA_ >> 11, lA = rA_ & 2047;
            int bB = rB_ >> 11, lB = rB_ & 2047;
            size_t iA = ((size_t)((bA * H_ + hh) * L_) + lA) * DH_ + dh;
            size_t iB = ((size_t)((bB * H_ + hh) * L_) + lB) * DH_ + dh;
            bf16 h0 = __float2bfloat16(v00), h1 = __float2bfloat16(v01);
            *(uint32_t*)(oHi + iA) = pack2(h0, h1);
            *(uint32_t*)(oLo + iA) = pack2(
                __float2bfloat16(v00 - __bfloat162float(h0)),
                __float2bfloat16(v01 - __bfloat162float(h1)));
            h0 = __float2bfloat16(v10); h1 = __float2bfloat16(v11);
            *(uint32_t*)(oHi + iB) = pack2(h0, h1);
            *(uint32_t*)(oLo + iB) = pack2(
                __float2bfloat16(v10 - __bfloat162float(h0)),
                __float2bfloat16(v11 - __bfloat162float(h1)));
        }
    }
}

// =====================================================================
// Fused attention: 128 thr, q-tile 64, key-tile 64, TRIPLE-buffered
// cp.async (depth-2 prefetch), one __syncthreads per iteration.
// natural regs (~196) -> 2 CTAs/SM via smem 111616.
// =====================================================================
#define PK 144
#define F_KB(st)  (1024 + (st) * 18432)           // K hi at +0, lo at +9216
#define F_VB(st)  (56320 + (st) * 18432)          // V hi at +0, lo at +9216
#define F_MB(st)  ((st) * 256)
#define F_TOTAL   111616

__global__ void __launch_bounds__(128, 2)
attn_fused(const bf16* __restrict__ qhi, const bf16* __restrict__ qlo,
           const bf16* __restrict__ khi, const bf16* __restrict__ klo,
           const bf16* __restrict__ vthi, const bf16* __restrict__ vtlo,
           const int*  __restrict__ mask,
           float* __restrict__ attn, float* __restrict__ ctx,
           float* __restrict__ invl_out)
{
    extern __shared__ char sm_[];
    const uint32_t sb = smem_u32(sm_);
    const int t = threadIdx.x, lane = t & 31, w = t >> 5, qq = lane & 3;
    const int q0 = blockIdx.x * 64, h = blockIdx.y, b = blockIdx.z;
    const size_t hb = (size_t)(b * H_ + h) * L_;
    const size_t headoff = hb * DH_;
    const int m0 = w * 16;
    const int rB = (lane & 7) + ((lane & 16) >> 1);
    const int cB = (lane >> 3) & 1;
    const int rA = lane & 15, cA = lane >> 4;
    const int r0 = m0 + (lane >> 2);

    // ---- Q fragments (staged through K stage-0 buffer) ----
#pragma unroll
    for (int e = 0; e < 4; e++) {
        int i = t + e * 128;
        int row = i >> 3, c16 = i & 7;
        *(uint4*)(sm_ + F_KB(0) + row * PK + c16 * 16) =
            *(const uint4*)(qhi + headoff + (size_t)(q0 + row) * DH_ + c16 * 8);
        *(uint4*)(sm_ + F_KB(0) + 9216 + row * PK + c16 * 16) =
            *(const uint4*)(qlo + headoff + (size_t)(q0 + row) * DH_ + c16 * 8);
    }
    __syncthreads();
    uint32_t qh[4][4], ql[4][4];
#pragma unroll
    for (int ks = 0; ks < 4; ks++) {
        LDSM4(qh[ks][0], qh[ks][1], qh[ks][2], qh[ks][3],
              sb + F_KB(0) + (m0 + rA) * PK + ks * 32 + cA * 16);
        LDSM4(ql[ks][0], ql[ks][1], ql[ks][2], ql[ks][3],
              sb + F_KB(0) + 9216 + (m0 + rA) * PK + ks * 32 + cA * 16);
    }
    __syncthreads();

#define PREFETCH(kt_, st_)                                                    \
    do {                                                                      \
        uint32_t kh_ = sb + F_KB(st_);                                        \
        uint32_t vh_ = sb + F_VB(st_);                                        \
        const bf16* kg = khi + headoff + (size_t)((kt_) * 64) * DH_;          \
        const bf16* lg = klo + headoff + (size_t)((kt_) * 64) * DH_;          \
        const bf16* vg = vthi + headoff + (kt_) * 64;                         \
        const bf16* wg = vtlo + headoff + (kt_) * 64;                         \
        _Pragma("unroll")                                                     \
        for (int e = 0; e < 4; e++) {                                         \
            int i = t + e * 128;                                              \
            int row = i >> 3, c16 = i & 7;                                    \
            CPA(kh_ + row * PK + c16 * 16, kg + (size_t)row * DH_ + c16 * 8); \
            CPA(kh_ + 9216 + row * PK + c16 * 16,                             \
                lg + (size_t)row * DH_ + c16 * 8);                            \
            CPA(vh_ + row * PK + c16 * 16, vg + (size_t)row * L_ + c16 * 8);  \
            CPA(vh_ + 9216 + row * PK + c16 * 16,                             \
                wg + (size_t)row * L_ + c16 * 8);                             \
        }                                                                     \
        if (t < 16)                                                           \
            CPA(sb + F_MB(st_) + t * 16,                                      \
                mask + b * L_ + (kt_) * 64 + t * 4);                          \
        CPC();                                                                \
    } while (0)

    PREFETCH(0, 0);
    PREFETCH(1, 1);

    float O[8][4];
#pragma unroll
    for (int i = 0; i < 8; i++)
#pragma unroll
        for (int j = 0; j < 4; j++) O[i][j] = 0.f;
    float lrunA = 0.f, lrunB = 0.f;

#pragma unroll 1
    for (int kt6 = 0; kt6 < 32; kt6++) {
        const int st = kt6 % 3;
        if (kt6 < 31) { CPW1(); } else { CPW0(); }
        __syncthreads();                 // stage st visible; stage (kt6-1)%3 free
        if (kt6 < 30) PREFETCH(kt6 + 2, (kt6 + 2) % 3);

        const uint32_t khb = sb + F_KB(st);
        const uint32_t vhb = sb + F_VB(st);
        const int* mi = (const int*)(sm_ + F_MB(st));

        float S[8][4];
#pragma unroll
        for (int i = 0; i < 8; i++)
#pragma unroll
            for (int j = 0; j < 4; j++) S[i][j] = 0.f;

#pragma unroll
        for (int ks = 0; ks < 4; ks++) {
#pragma unroll
            for (int n2 = 0; n2 < 4; n2++) {
                uint32_t b0, b1, b2, b3;
                uint32_t ad = khb + (n2 * 16 + rB) * PK + ks * 32 + cB * 16;
                LDSM4(b0, b1, b2, b3, ad);
                MMA4(S[2 * n2],     qh[ks][0], qh[ks][1], qh[ks][2], qh[ks][3], b0, b1);
                MMA4(S[2 * n2 + 1], qh[ks][0], qh[ks][1], qh[ks][2], qh[ks][3], b2, b3);
                MMA4(S[2 * n2],     ql[ks][0], ql[ks][1], ql[ks][2], ql[ks][3], b0, b1);
                MMA4(S[2 * n2 + 1], ql[ks][0], ql[ks][1], ql[ks][2], ql[ks][3], b2, b3);
                LDSM4(b0, b1, b2, b3, ad + 9216);
                MMA4(S[2 * n2],     qh[ks][0], qh[ks][1], qh[ks][2], qh[ks][3], b0, b1);
                MMA4(S[2 * n2 + 1], qh[ks][0], qh[ks][1], qh[ks][2], qh[ks][3], b2, b3);
            }
        }

        float* arow0 = attn + (hb + q0 + r0) * (size_t)L_ + kt6 * 64;
        float* arow1 = arow0 + 8 * L_;
#pragma unroll
        for (int nt = 0; nt < 8; nt++) {
            int c0 = nt * 8 + qq * 2;
            bool k0m = mi[c0] != 0, k1m = mi[c0 + 1] != 0;
            float e0 = k0m ? 0.f : __expf(S[nt][0] * 0.125f);
            float e1 = k1m ? 0.f : __expf(S[nt][1] * 0.125f);
            float e2 = k0m ? 0.f : __expf(S[nt][2] * 0.125f);
            float e3 = k1m ? 0.f : __expf(S[nt][3] * 0.125f);
            lrunA += e0 + e1; lrunB += e2 + e3;
            S[nt][0] = e0; S[nt][1] = e1; S[nt][2] = e2; S[nt][3] = e3;
            *(float2*)(arow0 + c0) = make_float2(e0, e1);
            *(float2*)(arow1 + c0) = make_float2(e2, e3);
        }

#pragma unroll
        for (int ks = 0; ks < 4; ks++) {
            bf16 h00 = __float2bfloat16(S[2 * ks][0]);
            bf16 h01 = __float2bfloat16(S[2 * ks][1]);
            bf16 h02 = __float2bfloat16(S[2 * ks][2]);
            bf16 h03 = __float2bfloat16(S[2 * ks][3]);
            bf16 h10 = __float2bfloat16(S[2 * ks + 1][0]);
            bf16 h11 = __float2bfloat16(S[2 * ks + 1][1]);
            bf16 h12 = __float2bfloat16(S[2 * ks + 1][2]);
            bf16 h13 = __float2bfloat16(S[2 * ks + 1][3]);
            uint32_t a0h = pack2(h00, h01), a1h = pack2(h02, h03);
            uint32_t a2h = pack2(h10, h11), a3h = pack2(h12, h13);
            uint32_t a0l = pack2(
                __float2bfloat16(S[2 * ks][0] - __bfloat162float(h00)),
                __float2bfloat16(S[2 * ks][1] - __bfloat162float(h01)));
            uint32_t a1l = pack2(
                __float2bfloat16(S[2 * ks][2] - __bfloat162float(h02)),
                __float2bfloat16(S[2 * ks][3] - __bfloat162float(h03)));
            uint32_t a2l = pack2(
                __float2bfloat16(S[2 * ks + 1][0] - __bfloat162float(h10)),
                __float2bfloat16(S[2 * ks + 1][1] - __bfloat162float(h11)));
            uint32_t a3l = pack2(
                __float2bfloat16(S[2 * ks + 1][2] - __bfloat162float(h12)),
                __float2bfloat16(S[2 * ks + 1][3] - __bfloat162float(h13)));
#pragma unroll
            for (int n2 = 0; n2 < 4; n2++) {
                uint32_t b0, b1, b2, b3;
                uint32_t ad = vhb + (n2 * 16 + rB) * PK + ks * 32 + cB * 16;
                LDSM4(b0, b1, b2, b3, ad);
                MMA4(O[2 * n2],     a0h, a1h, a2h, a3h, b0, b1);
                MMA4(O[2 * n2 + 1], a0h, a1h, a2h, a3h, b2, b3);
                MMA4(O[2 * n2],     a0l, a1l, a2l, a3l, b0, b1);
                MMA4(O[2 * n2 + 1], a0l, a1l, a2l, a3l, b2, b3);
                LDSM4(b0, b1, b2, b3, ad + 9216);
                MMA4(O[2 * n2],     a0h, a1h, a2h, a3h, b0, b1);
                MMA4(O[2 * n2 + 1], a0h, a1h, a2h, a3h, b2, b3);
            }
        }
    }
#undef PREFETCH

    lrunA += __shfl_xor_sync(0xffffffffu, lrunA, 1);
    lrunA += __shfl_xor_sync(0xffffffffu, lrunA, 2);
    lrunB += __shfl_xor_sync(0xffffffffu, lrunB, 1);
    lrunB += __shfl_xor_sync(0xffffffffu, lrunB, 2);
    float ilA = 1.f / lrunA, ilB = 1.f / lrunB;
    if (qq == 0) {
        invl_out[hb + q0 + r0]     = ilA;
        invl_out[hb + q0 + r0 + 8] = ilB;
    }
    int rg = q0 + r0;
#pragma unroll
    for (int nt = 0; nt < 8; nt++) {
        int d = nt * 8 + qq * 2;
        *(float2*)(ctx + ((size_t)b * L_ + rg) * D_ + h * 64 + d) =
            make_float2(O[nt][0] * ilA, O[nt][1] * ilA);
        *(float2*)(ctx + ((size_t)b * L_ + rg + 8) * D_ + h * 64 + d) =
            make_float2(O[nt][2] * ilB, O[nt][3] * ilB);
    }
}

// ---------------- streaming normalize of the attn strip --------------------
__global__ void __launch_bounds__(512, 2)
scale_attn(float4* __restrict__ a, const float* __restrict__ invl)
{
    const size_t n4 = (size_t)B_ * H_ * L_ * L_ / 4;
    size_t i = (size_t)blockIdx.x * blockDim.x + threadIdx.x;
    const size_t stride = (size_t)gridDim.x * blockDim.x;
    for (; i < n4; i += stride) {
        float s = __ldg(invl + (i >> 9));
        float4 v = a[i];
        v.x *= s; v.y *= s; v.z *= s; v.w *= s;
        a[i] = v;
    }
}

extern "C" void kernel_launch(void* const* d_in, const int* in_sizes, int n_in,
                              void* d_out, int out_size)
{
    const float* q    = (const float*)d_in[0];
    const float* k    = (const float*)d_in[1];
    const float* v    = (const float*)d_in[2];
    const int*   mask = (const int*)  d_in[3];
    const float* wq_w = (const float*)d_in[4];
    const float* wq_b = (const float*)d_in[5];
    const float* wk_w = (const float*)d_in[6];
    const float* wk_b = (const float*)d_in[7];
    const float* wv_w = (const float*)d_in[8];
    const float* wv_b = (const float*)d_in[9];
    const float* wo_w = (const float*)d_in[10];
    const float* wo_b = (const float*)d_in[11];

    float* out = (float*)d_out;
    const long long OUT_E  = (long long)B_ * L_ * D_;
    const long long ATTN_E = (long long)B_ * H_ * L_ * L_;

    float* attn_ptr;
    if ((long long)out_size >= OUT_E + ATTN_E) {
        attn_ptr = out + OUT_E;
    } else {
        void* p = nullptr;
        cudaGetSymbolAddress(&p, g_attn_fb);
        attn_ptr = (float*)p;
    }

    bf16 *qhi, *qlo, *khi, *klo, *vthi, *vtlo;
    float *ctx, *invl;
    { void* p; cudaGetSymbolAddress(&p, g_qhi);  qhi  = (bf16*)p; }
    { void* p; cudaGetSymbolAddress(&p, g_qlo);  qlo  = (bf16*)p; }
    { void* p; cudaGetSymbolAddress(&p, g_khi);  khi  = (bf16*)p; }
    { void* p; cudaGetSymbolAddress(&p, g_klo);  klo  = (bf16*)p; }
    { void* p; cudaGetSymbolAddress(&p, g_vthi); vthi = (bf16*)p; }
    { void* p; cudaGetSymbolAddress(&p, g_vtlo); vtlo = (bf16*)p; }
    { void* p; cudaGetSymbolAddress(&p, g_ctx);  ctx  = (float*)p; }
    { void* p; cudaGetSymbolAddress(&p, g_invl); invl = (float*)p; }

    cudaFuncSetAttribute(gemm_mma,
        cudaFuncAttributeMaxDynamicSharedMemorySize, G_SM_TOTAL);
    cudaFuncSetAttribute(attn_fused,
        cudaFuncAttributeMaxDynamicSharedMemorySize, F_TOTAL);

    dim3 grid_proj(D_ / 128, (B_ * L_) / 128);   // (4, 64)

    gemm_mma<<<grid_proj, 256, G_SM_TOTAL>>>(q, wq_w, wq_b, nullptr, qhi, qlo, 1);
    gemm_mma<<<grid_proj, 256, G_SM_TOTAL>>>(k, wk_w, wk_b, nullptr, khi, klo, 1);
    gemm_mma<<<grid_proj, 256, G_SM_TOTAL>>>(v, wv_w, wv_b, nullptr, vthi, vtlo, 2);

    dim3 grid_attn(L_ / 64, H_, B_);             // (32, 8, 4)
    attn_fused<<<grid_attn, 128, F_TOTAL>>>(qhi, qlo, khi, klo, vthi, vtlo,
                                            mask, attn_ptr, ctx, invl);

    scale_attn<<<16384, 512>>>((float4*)attn_ptr, invl);

    gemm_mma<<<grid_proj, 256, G_SM_TOTAL>>>(ctx, wo_w, wo_b, out,
                                             nullptr, nullptr, 0);
}

// round 11
// speedup vs baseline: 1.5316x; 1.0280x over previous
#include <cuda_runtime.h>
#include <cuda_bf16.h>
#include <cstdint>
#include <cstddef>

#define B_  4
#define L_  2048
#define D_  512
#define H_  8
#define DH_ 64

typedef __nv_bfloat16 bf16;

#define PROJ_E ((size_t)B_ * H_ * L_ * DH_)
__device__ bf16  g_qhi[PROJ_E];
__device__ bf16  g_qlo[PROJ_E];
__device__ bf16  g_khi[PROJ_E];
__device__ bf16  g_klo[PROJ_E];
__device__ bf16  g_vthi[PROJ_E];    // V transposed: [B,H,dh,L]
__device__ bf16  g_vtlo[PROJ_E];
__device__ float g_ctx[(size_t)B_ * L_ * D_];
__device__ float g_invl[(size_t)B_ * H_ * L_];
__device__ float g_attn_fb[(size_t)B_ * H_ * L_ * L_];

__device__ __forceinline__ uint32_t smem_u32(const void* p) {
    uint32_t a;
    asm("{ .reg .u64 t; cvta.to.shared.u64 t, %1; cvt.u32.u64 %0, t; }"
        : "=r"(a) : "l"(p));
    return a;
}

#define LDSM4(R0, R1, R2, R3, A) \
    asm volatile("ldmatrix.sync.aligned.m8n8.x4.shared.b16 {%0,%1,%2,%3}, [%4];" \
                 : "=r"(R0), "=r"(R1), "=r"(R2), "=r"(R3) : "r"(A))

#define MMA4(D, A0, A1, A2, A3, Bb0, Bb1) \
    asm volatile("mma.sync.aligned.m16n8k16.row.col.f32.bf16.bf16.f32 " \
                 "{%0,%1,%2,%3}, {%4,%5,%6,%7}, {%8,%9}, {%0,%1,%2,%3};" \
                 : "+f"((D)[0]), "+f"((D)[1]), "+f"((D)[2]), "+f"((D)[3]) \
                 : "r"(A0), "r"(A1), "r"(A2), "r"(A3), "r"(Bb0), "r"(Bb1))

#define CPA(dst, src) \
    asm volatile("cp.async.ca.shared.global [%0], [%1], 16;" \
                 :: "r"((uint32_t)(dst)), "l"(src) : "memory")
#define CPC()  asm volatile("cp.async.commit_group;" ::: "memory")
#define CPW0() asm volatile("cp.async.wait_group 0;" ::: "memory")

__device__ __forceinline__ uint32_t pack2(bf16 a, bf16 b) {
    return (uint32_t)__bfloat16_as_ushort(a) |
           ((uint32_t)__bfloat16_as_ushort(b) << 16);
}

// =====================================================================
// GEMM body, templated on epilogue mode.
// MODE 0: fp32 flat; MODE 1: bf16 hi/lo [B,H,L,64] (scaled); MODE 2: [B,H,64,L]
// =====================================================================
#define GP 144
#define G_XHI 0
#define G_XLO 18432
#define G_WHI 36864
#define G_WLO 55296
#define G_SM_TOTAL 73728
#define T_PT  272
#define T_HI  0
#define T_LO  36864

template <int MODE>
__device__ __forceinline__ void
gemm_body(const float* __restrict__ X, const float* __restrict__ W,
          const float* __restrict__ bias, float oscale,
          float* __restrict__ out32, bf16* __restrict__ oHi,
          bf16* __restrict__ oLo, int n0, int mb,
          char* sm_, uint32_t sb)
{
    const int t = threadIdx.x, lane = t & 31, w = t >> 5, qq = lane & 3;
    const int m0 = w * 16;
    const int rB = (lane & 7) + ((lane & 16) >> 1);
    const int cB = (lane >> 3) & 1;
    const int rA = lane & 15, cA = lane >> 4;

    float S[16][4];
#pragma unroll
    for (int i = 0; i < 16; i++)
#pragma unroll
        for (int j = 0; j < 4; j++) S[i][j] = 0.f;

    float4 xr[8], wr[8];
#define LOADCHUNK(kc_)                                                        \
    do {                                                                      \
        _Pragma("unroll")                                                     \
        for (int e = 0; e < 8; e++) {                                         \
            int i = t + e * 256;                                              \
            int row = i >> 4, c4 = (i & 15) * 4;                              \
            xr[e] = *(const float4*)(X + (size_t)(mb + row) * D_ + (kc_) + c4);\
            wr[e] = *(const float4*)(W + (size_t)(n0 + row) * D_ + (kc_) + c4);\
        }                                                                     \
    } while (0)

    LOADCHUNK(0);

#pragma unroll 1
    for (int kc6 = 0; kc6 < 8; kc6++) {
        __syncthreads();
#pragma unroll
        for (int e = 0; e < 8; e++) {
            int i = t + e * 256;
            int row = i >> 4, c4 = (i & 15) * 4;
            float4 x = xr[e];
            bf16 h0 = __float2bfloat16(x.x), h1 = __float2bfloat16(x.y);
            bf16 h2 = __float2bfloat16(x.z), h3 = __float2bfloat16(x.w);
            *(uint2*)(sm_ + G_XHI + row * GP + c4 * 2) =
                make_uint2(pack2(h0, h1), pack2(h2, h3));
            *(uint2*)(sm_ + G_XLO + row * GP + c4 * 2) = make_uint2(
                pack2(__float2bfloat16(x.x - __bfloat162float(h0)),
                      __float2bfloat16(x.y - __bfloat162float(h1))),
                pack2(__float2bfloat16(x.z - __bfloat162float(h2)),
                      __float2bfloat16(x.w - __bfloat162float(h3))));
            float4 wv = wr[e];
            h0 = __float2bfloat16(wv.x); h1 = __float2bfloat16(wv.y);
            h2 = __float2bfloat16(wv.z); h3 = __float2bfloat16(wv.w);
            *(uint2*)(sm_ + G_WHI + row * GP + c4 * 2) =
                make_uint2(pack2(h0, h1), pack2(h2, h3));
            *(uint2*)(sm_ + G_WLO + row * GP + c4 * 2) = make_uint2(
                pack2(__float2bfloat16(wv.x - __bfloat162float(h0)),
                      __float2bfloat16(wv.y - __bfloat162float(h1))),
                pack2(__float2bfloat16(wv.z - __bfloat162float(h2)),
                      __float2bfloat16(wv.w - __bfloat162float(h3))));
        }
        __syncthreads();
        if (kc6 < 7) LOADCHUNK((kc6 + 1) * 64);

#pragma unroll
        for (int ks = 0; ks < 4; ks++) {
            uint32_t ah0, ah1, ah2, ah3, al0, al1, al2, al3;
            LDSM4(ah0, ah1, ah2, ah3,
                  sb + G_XHI + (m0 + rA) * GP + ks * 32 + cA * 16);
            LDSM4(al0, al1, al2, al3,
                  sb + G_XLO + (m0 + rA) * GP + ks * 32 + cA * 16);
#pragma unroll
            for (int n2 = 0; n2 < 8; n2++) {
                uint32_t b0, b1, b2, b3;
                uint32_t ad = sb + G_WHI + (n2 * 16 + rB) * GP + ks * 32 + cB * 16;
                LDSM4(b0, b1, b2, b3, ad);
                MMA4(S[2 * n2],     ah0, ah1, ah2, ah3, b0, b1);
                MMA4(S[2 * n2 + 1], ah0, ah1, ah2, ah3, b2, b3);
                MMA4(S[2 * n2],     al0, al1, al2, al3, b0, b1);
                MMA4(S[2 * n2 + 1], al0, al1, al2, al3, b2, b3);
                LDSM4(b0, b1, b2, b3, ad + (G_WLO - G_WHI));
                MMA4(S[2 * n2],     ah0, ah1, ah2, ah3, b0, b1);
                MMA4(S[2 * n2 + 1], ah0, ah1, ah2, ah3, b2, b3);
            }
        }
    }
#undef LOADCHUNK

    const int rA_ = mb + m0 + (lane >> 2);
    const int rB_ = rA_ + 8;

    if (MODE == 2) {
        __syncthreads();
        const int mA = m0 + (lane >> 2), mB = mA + 8;
#pragma unroll
        for (int nt = 0; nt < 16; nt++) {
            int c = nt * 8 + qq * 2;
            float bs0 = bias[n0 + c], bs1 = bias[n0 + c + 1];
            float v00 = S[nt][0] + bs0, v01 = S[nt][1] + bs1;
            float v10 = S[nt][2] + bs0, v11 = S[nt][3] + bs1;
            bf16 h;
            h = __float2bfloat16(v00);
            *(bf16*)(sm_ + T_HI + c * T_PT + mA * 2) = h;
            *(bf16*)(sm_ + T_LO + c * T_PT + mA * 2) =
                __float2bfloat16(v00 - __bfloat162float(h));
            h = __float2bfloat16(v01);
            *(bf16*)(sm_ + T_HI + (c + 1) * T_PT + mA * 2) = h;
            *(bf16*)(sm_ + T_LO + (c + 1) * T_PT + mA * 2) =
                __float2bfloat16(v01 - __bfloat162float(h));
            h = __float2bfloat16(v10);
            *(bf16*)(sm_ + T_HI + c * T_PT + mB * 2) = h;
            *(bf16*)(sm_ + T_LO + c * T_PT + mB * 2) =
                __float2bfloat16(v10 - __bfloat162float(h));
            h = __float2bfloat16(v11);
            *(bf16*)(sm_ + T_HI + (c + 1) * T_PT + mB * 2) = h;
            *(bf16*)(sm_ + T_LO + (c + 1) * T_PT + mB * 2) =
                __float2bfloat16(v11 - __bfloat162float(h));
        }
        __syncthreads();
        const int bA = mb >> 11, lA0 = mb & 2047;
        const int cl = t >> 1, half = t & 1;
        const int hh = (n0 + cl) >> 6, dh = (n0 + cl) & 63;
        size_t gbase = ((size_t)((bA * H_ + hh) * DH_) + dh) * L_ + lA0 + half * 64;
        const char* srcH = sm_ + T_HI + cl * T_PT + half * 128;
        const char* srcL = sm_ + T_LO + cl * T_PT + half * 128;
#pragma unroll
        for (int e = 0; e < 8; e++) {
            *(uint4*)(oHi + gbase + e * 8) = *(const uint4*)(srcH + e * 16);
            *(uint4*)(oLo + gbase + e * 8) = *(const uint4*)(srcL + e * 16);
        }
        return;
    }

#pragma unroll
    for (int nt = 0; nt < 16; nt++) {
        int c = n0 + nt * 8 + qq * 2;
        float bs0 = bias[c], bs1 = bias[c + 1];
        float v00 = S[nt][0] + bs0, v01 = S[nt][1] + bs1;
        float v10 = S[nt][2] + bs0, v11 = S[nt][3] + bs1;
        if (MODE == 0) {
            *(float2*)(out32 + (size_t)rA_ * D_ + c) = make_float2(v00, v01);
            *(float2*)(out32 + (size_t)rB_ * D_ + c) = make_float2(v10, v11);
        } else {
            v00 *= oscale; v01 *= oscale; v10 *= oscale; v11 *= oscale;
            int hh = c >> 6, dh = c & 63;
            int bA = rA_ >> 11, lA = rA_ & 2047;
            int bB = rB_ >> 11, lB = rB_ & 2047;
            size_t iA = ((size_t)((bA * H_ + hh) * L_) + lA) * DH_ + dh;
            size_t iB = ((size_t)((bB * H_ + hh) * L_) + lB) * DH_ + dh;
            bf16 h0 = __float2bfloat16(v00), h1 = __float2bfloat16(v01);
            *(uint32_t*)(oHi + iA) = pack2(h0, h1);
            *(uint32_t*)(oLo + iA) = pack2(
                __float2bfloat16(v00 - __bfloat162float(h0)),
                __float2bfloat16(v01 - __bfloat162float(h1)));
            h0 = __float2bfloat16(v10); h1 = __float2bfloat16(v11);
            *(uint32_t*)(oHi + iB) = pack2(h0, h1);
            *(uint32_t*)(oLo + iB) = pack2(
                __float2bfloat16(v10 - __bfloat162float(h0)),
                __float2bfloat16(v11 - __bfloat162float(h1)));
        }
    }
}

__global__ void __launch_bounds__(256, 1)
gemm_proj(const float* __restrict__ X, const float* __restrict__ W,
          const float* __restrict__ bias, float oscale,
          bf16* __restrict__ oHi, bf16* __restrict__ oLo)
{
    extern __shared__ char sm_[];
    gemm_body<1>(X, W, bias, oscale, nullptr, oHi, oLo,
                 blockIdx.x * 128, blockIdx.y * 128, sm_, smem_u32(sm_));
}

__global__ void __launch_bounds__(256, 1)
gemm_projT(const float* __restrict__ X, const float* __restrict__ W,
           const float* __restrict__ bias,
           bf16* __restrict__ oHi, bf16* __restrict__ oLo)
{
    extern __shared__ char sm_[];
    gemm_body<2>(X, W, bias, 1.f, nullptr, oHi, oLo,
                 blockIdx.x * 128, blockIdx.y * 128, sm_, smem_u32(sm_));
}

// ---- fused out-GEMM + attn normalization: grid.x = 1024 ----
__global__ void __launch_bounds__(256, 1)
out_scale(const float* __restrict__ ctx, const float* __restrict__ wo,
          const float* __restrict__ bo, float* __restrict__ out,
          float4* __restrict__ attn4, const float* __restrict__ invl)
{
    extern __shared__ char sm_[];
    const int bx = blockIdx.x;
    if ((bx & 3) == 0) {
        int idx = bx >> 2;                       // 0..255
        gemm_body<0>(ctx, wo, bo, 1.f, out, nullptr, nullptr,
                     (idx & 3) * 128, (idx >> 2) * 128, sm_, smem_u32(sm_));
    } else {
        const size_t n4 = (size_t)B_ * H_ * L_ * L_ / 4;
        int sidx = bx - ((bx + 3) >> 2);         // 0..767
        size_t i = (size_t)sidx * 256 + threadIdx.x;
        const size_t stride = (size_t)768 * 256;
        for (; i < n4; i += stride) {
            float s = __ldg(invl + (i >> 9));
            float4 vv = attn4[i];
            vv.x *= s; vv.y *= s; vv.z *= s; vv.w *= s;
            attn4[i] = vv;
        }
    }
}

// =====================================================================
// Fused attention: R7 double-buffer core + B-fragment preload ILP.
// Q pre-scaled by 0.125 at projection.
// =====================================================================
#define PK 144
#define F_M0   0
#define F_M1   256
#define F_KHI0 1024
#define F_KLO0 (F_KHI0 + 9216)
#define F_KHI1 (F_KLO0 + 9216)
#define F_KLO1 (F_KHI1 + 9216)
#define F_VHI0 (F_KLO1 + 9216)
#define F_VLO0 (F_VHI0 + 9216)
#define F_VHI1 (F_VLO0 + 9216)
#define F_VLO1 (F_VHI1 + 9216)
#define F_TOTAL (F_VLO1 + 9216)   // 74752

__global__ void __launch_bounds__(128, 2)
attn_fused(const bf16* __restrict__ qhi, const bf16* __restrict__ qlo,
           const bf16* __restrict__ khi, const bf16* __restrict__ klo,
           const bf16* __restrict__ vthi, const bf16* __restrict__ vtlo,
           const int*  __restrict__ mask,
           float* __restrict__ attn, float* __restrict__ ctx,
           float* __restrict__ invl_out)
{
    extern __shared__ char sm_[];
    const uint32_t sb = smem_u32(sm_);
    const int t = threadIdx.x, lane = t & 31, w = t >> 5, qq = lane & 3;
    const int q0 = blockIdx.x * 64, h = blockIdx.y, b = blockIdx.z;
    const size_t hb = (size_t)(b * H_ + h) * L_;
    const size_t headoff = hb * DH_;
    const int m0 = w * 16;
    const int rB = (lane & 7) + ((lane & 16) >> 1);
    const int cB = (lane >> 3) & 1;
    const int rA = lane & 15, cA = lane >> 4;
    const int r0 = m0 + (lane >> 2);

#pragma unroll
    for (int e = 0; e < 4; e++) {
        int i = t + e * 128;
        int row = i >> 3, c16 = i & 7;
        *(uint4*)(sm_ + F_KHI0 + row * PK + c16 * 16) =
            *(const uint4*)(qhi + headoff + (size_t)(q0 + row) * DH_ + c16 * 8);
        *(uint4*)(sm_ + F_KLO0 + row * PK + c16 * 16) =
            *(const uint4*)(qlo + headoff + (size_t)(q0 + row) * DH_ + c16 * 8);
    }
    __syncthreads();
    uint32_t qh[4][4], ql[4][4];
#pragma unroll
    for (int ks = 0; ks < 4; ks++) {
        LDSM4(qh[ks][0], qh[ks][1], qh[ks][2], qh[ks][3],
              sb + F_KHI0 + (m0 + rA) * PK + ks * 32 + cA * 16);
        LDSM4(ql[ks][0], ql[ks][1], ql[ks][2], ql[ks][3],
              sb + F_KLO0 + (m0 + rA) * PK + ks * 32 + cA * 16);
    }
    __syncthreads();

#define PREFETCH(kt_, par_)                                                   \
    do {                                                                      \
        uint32_t kh_ = sb + ((par_) ? F_KHI1 : F_KHI0);                       \
        uint32_t vh_ = sb + ((par_) ? F_VHI1 : F_VHI0);                       \
        const bf16* kg = khi + headoff + (size_t)((kt_) * 64) * DH_;          \
        const bf16* lg = klo + headoff + (size_t)((kt_) * 64) * DH_;          \
        const bf16* vg = vthi + headoff + (kt_) * 64;                         \
        const bf16* wg = vtlo + headoff + (kt_) * 64;                         \
        _Pragma("unroll")                                                     \
        for (int e = 0; e < 4; e++) {                                         \
            int i = t + e * 128;                                              \
            int row = i >> 3, c16 = i & 7;                                    \
            CPA(kh_ + row * PK + c16 * 16, kg + (size_t)row * DH_ + c16 * 8); \
            CPA(kh_ + 9216 + row * PK + c16 * 16,                             \
                lg + (size_t)row * DH_ + c16 * 8);                            \
            CPA(vh_ + row * PK + c16 * 16, vg + (size_t)row * L_ + c16 * 8);  \
            CPA(vh_ + 9216 + row * PK + c16 * 16,                             \
                wg + (size_t)row * L_ + c16 * 8);                             \
        }                                                                     \
        if (t < 16)                                                           \
            CPA(sb + ((par_) ? F_M1 : F_M0) + t * 16,                         \
                mask + b * L_ + (kt_) * 64 + t * 4);                          \
        CPC();                                                                \
    } while (0)

    PREFETCH(0, 0);

    float O[8][4];
#pragma unroll
    for (int i = 0; i < 8; i++)
#pragma unroll
        for (int j = 0; j < 4; j++) O[i][j] = 0.f;
    float lrunA = 0.f, lrunB = 0.f;

#pragma unroll 1
    for (int kt6 = 0; kt6 < 32; kt6++) {
        const int par = kt6 & 1;
        CPW0();
        __syncthreads();
        if (kt6 < 31) PREFETCH(kt6 + 1, par ^ 1);

        const uint32_t khb = sb + (par ? F_KHI1 : F_KHI0);
        const uint32_t vhb = sb + (par ? F_VHI1 : F_VHI0);
        const int* mi = (const int*)(sm_ + (par ? F_M1 : F_M0));

        float S[8][4];
#pragma unroll
        for (int i = 0; i < 8; i++)
#pragma unroll
            for (int j = 0; j < 4; j++) S[i][j] = 0.f;

        // S = Q K^T (3-term), B-frags preloaded for ILP
#pragma unroll
        for (int ks = 0; ks < 4; ks++) {
            uint32_t bh[4][4];
#pragma unroll
            for (int n2 = 0; n2 < 4; n2++)
                LDSM4(bh[n2][0], bh[n2][1], bh[n2][2], bh[n2][3],
                      khb + (n2 * 16 + rB) * PK + ks * 32 + cB * 16);
#pragma unroll
            for (int n2 = 0; n2 < 4; n2++) {
                MMA4(S[2 * n2],     qh[ks][0], qh[ks][1], qh[ks][2], qh[ks][3],
                     bh[n2][0], bh[n2][1]);
                MMA4(S[2 * n2 + 1], qh[ks][0], qh[ks][1], qh[ks][2], qh[ks][3],
                     bh[n2][2], bh[n2][3]);
            }
#pragma unroll
            for (int n2 = 0; n2 < 4; n2++) {
                MMA4(S[2 * n2],     ql[ks][0], ql[ks][1], ql[ks][2], ql[ks][3],
                     bh[n2][0], bh[n2][1]);
                MMA4(S[2 * n2 + 1], ql[ks][0], ql[ks][1], ql[ks][2], ql[ks][3],
                     bh[n2][2], bh[n2][3]);
            }
#pragma unroll
            for (int n2 = 0; n2 < 4; n2++) {
                uint32_t c0, c1, c2, c3;
                LDSM4(c0, c1, c2, c3,
                      khb + 9216 + (n2 * 16 + rB) * PK + ks * 32 + cB * 16);
                MMA4(S[2 * n2],     qh[ks][0], qh[ks][1], qh[ks][2], qh[ks][3],
                     c0, c1);
                MMA4(S[2 * n2 + 1], qh[ks][0], qh[ks][1], qh[ks][2], qh[ks][3],
                     c2, c3);
            }
        }

        // e = exp(s) (Q pre-scaled; masked -> 0), rowsum, write strip
        float* arow0 = attn + (hb + q0 + r0) * (size_t)L_ + kt6 * 64;
        float* arow1 = arow0 + 8 * L_;
#pragma unroll
        for (int nt = 0; nt < 8; nt++) {
            int c0 = nt * 8 + qq * 2;
            bool k0m = mi[c0] != 0, k1m = mi[c0 + 1] != 0;
            float e0 = k0m ? 0.f : __expf(S[nt][0]);
            float e1 = k1m ? 0.f : __expf(S[nt][1]);
            float e2 = k0m ? 0.f : __expf(S[nt][2]);
            float e3 = k1m ? 0.f : __expf(S[nt][3]);
            lrunA += e0 + e1; lrunB += e2 + e3;
            S[nt][0] = e0; S[nt][1] = e1; S[nt][2] = e2; S[nt][3] = e3;
            *(float2*)(arow0 + c0) = make_float2(e0, e1);
            *(float2*)(arow1 + c0) = make_float2(e2, e3);
        }

        // O += e * V  (P in regs), V-frags preloaded for ILP
#pragma unroll
        for (int ks = 0; ks < 4; ks++) {
            bf16 h00 = __float2bfloat16(S[2 * ks][0]);
            bf16 h01 = __float2bfloat16(S[2 * ks][1]);
            bf16 h02 = __float2bfloat16(S[2 * ks][2]);
            bf16 h03 = __float2bfloat16(S[2 * ks][3]);
            bf16 h10 = __float2bfloat16(S[2 * ks + 1][0]);
            bf16 h11 = __float2bfloat16(S[2 * ks + 1][1]);
            bf16 h12 = __float2bfloat16(S[2 * ks + 1][2]);
            bf16 h13 = __float2bfloat16(S[2 * ks + 1][3]);
            uint32_t a0h = pack2(h00, h01), a1h = pack2(h02, h03);
            uint32_t a2h = pack2(h10, h11), a3h = pack2(h12, h13);
            uint32_t a0l = pack2(
                __float2bfloat16(S[2 * ks][0] - __bfloat162float(h00)),
                __float2bfloat16(S[2 * ks][1] - __bfloat162float(h01)));
            uint32_t a1l = pack2(
                __float2bfloat16(S[2 * ks][2] - __bfloat162float(h02)),
                __float2bfloat16(S[2 * ks][3] - __bfloat162float(h03)));
            uint32_t a2l = pack2(
                __float2bfloat16(S[2 * ks + 1][0] - __bfloat162float(h10)),
                __float2bfloat16(S[2 * ks + 1][1] - __bfloat162float(h11)));
            uint32_t a3l = pack2(
                __float2bfloat16(S[2 * ks + 1][2] - __bfloat162float(h12)),
                __float2bfloat16(S[2 * ks + 1][3] - __bfloat162float(h13)));
            uint32_t vh[4][4];
#pragma unroll
            for (int n2 = 0; n2 < 4; n2++)
                LDSM4(vh[n2][0], vh[n2][1], vh[n2][2], vh[n2][3],
                      vhb + (n2 * 16 + rB) * PK + ks * 32 + cB * 16);
#pragma unroll
            for (int n2 = 0; n2 < 4; n2++) {
                MMA4(O[2 * n2],     a0h, a1h, a2h, a3h, vh[n2][0], vh[n2][1]);
                MMA4(O[2 * n2 + 1], a0h, a1h, a2h, a3h, vh[n2][2], vh[n2][3]);
            }
#pragma unroll
            for (int n2 = 0; n2 < 4; n2++) {
                MMA4(O[2 * n2],     a0l, a1l, a2l, a3l, vh[n2][0], vh[n2][1]);
                MMA4(O[2 * n2 + 1], a0l, a1l, a2l, a3l, vh[n2][2], vh[n2][3]);
            }
#pragma unroll
            for (int n2 = 0; n2 < 4; n2++) {
                uint32_t c0, c1, c2, c3;
                LDSM4(c0, c1, c2, c3,
                      vhb + 9216 + (n2 * 16 + rB) * PK + ks * 32 + cB * 16);
                MMA4(O[2 * n2],     a0h, a1h, a2h, a3h, c0, c1);
                MMA4(O[2 * n2 + 1], a0h, a1h, a2h, a3h, c2, c3);
            }
        }
        __syncthreads();
    }
#undef PREFETCH

    lrunA += __shfl_xor_sync(0xffffffffu, lrunA, 1);
    lrunA += __shfl_xor_sync(0xffffffffu, lrunA, 2);
    lrunB += __shfl_xor_sync(0xffffffffu, lrunB, 1);
    lrunB += __shfl_xor_sync(0xffffffffu, lrunB, 2);
    float ilA = 1.f / lrunA, ilB = 1.f / lrunB;
    if (qq == 0) {
        invl_out[hb + q0 + r0]     = ilA;
        invl_out[hb + q0 + r0 + 8] = ilB;
    }
    int rg = q0 + r0;
#pragma unroll
    for (int nt = 0; nt < 8; nt++) {
        int d = nt * 8 + qq * 2;
        *(float2*)(ctx + ((size_t)b * L_ + rg) * D_ + h * 64 + d) =
            make_float2(O[nt][0] * ilA, O[nt][1] * ilA);
        *(float2*)(ctx + ((size_t)b * L_ + rg + 8) * D_ + h * 64 + d) =
            make_float2(O[nt][2] * ilB, O[nt][3] * ilB);
    }
}

extern "C" void kernel_launch(void* const* d_in, const int* in_sizes, int n_in,
                              void* d_out, int out_size)
{
    const float* q    = (const float*)d_in[0];
    const float* k    = (const float*)d_in[1];
    const float* v    = (const float*)d_in[2];
    const int*   mask = (const int*)  d_in[3];
    const float* wq_w = (const float*)d_in[4];
    const float* wq_b = (const float*)d_in[5];
    const float* wk_w = (const float*)d_in[6];
    const float* wk_b = (const float*)d_in[7];
    const float* wv_w = (const float*)d_in[8];
    const float* wv_b = (const float*)d_in[9];
    const float* wo_w = (const float*)d_in[10];
    const float* wo_b = (const float*)d_in[11];

    float* out = (float*)d_out;
    const long long OUT_E  = (long long)B_ * L_ * D_;
    const long long ATTN_E = (long long)B_ * H_ * L_ * L_;

    float* attn_ptr;
    if ((long long)out_size >= OUT_E + ATTN_E) {
        attn_ptr = out + OUT_E;
    } else {
        void* p = nullptr;
        cudaGetSymbolAddress(&p, g_attn_fb);
        attn_ptr = (float*)p;
    }

    bf16 *qhi, *qlo, *khi, *klo, *vthi, *vtlo;
    float *ctx, *invl;
    { void* p; cudaGetSymbolAddress(&p, g_qhi);  qhi  = (bf16*)p; }
    { void* p; cudaGetSymbolAddress(&p, g_qlo);  qlo  = (bf16*)p; }
    { void* p; cudaGetSymbolAddress(&p, g_khi);  khi  = (bf16*)p; }
    { void* p; cudaGetSymbolAddress(&p, g_klo);  klo  = (bf16*)p; }
    { void* p; cudaGetSymbolAddress(&p, g_vthi); vthi = (bf16*)p; }
    { void* p; cudaGetSymbolAddress(&p, g_vtlo); vtlo = (bf16*)p; }
    { void* p; cudaGetSymbolAddress(&p, g_ctx);  ctx  = (float*)p; }
    { void* p; cudaGetSymbolAddress(&p, g_invl); invl = (float*)p; }

    cudaFuncSetAttribute(gemm_proj,
        cudaFuncAttributeMaxDynamicSharedMemorySize, G_SM_TOTAL);
    cudaFuncSetAttribute(gemm_projT,
        cudaFuncAttributeMaxDynamicSharedMemorySize, G_SM_TOTAL);
    cudaFuncSetAttribute(out_scale,
        cudaFuncAttributeMaxDynamicSharedMemorySize, G_SM_TOTAL);
    cudaFuncSetAttribute(attn_fused,
        cudaFuncAttributeMaxDynamicSharedMemorySize, F_TOTAL);

    dim3 grid_proj(D_ / 128, (B_ * L_) / 128);   // (4, 64)

    gemm_proj<<<grid_proj, 256, G_SM_TOTAL>>>(q, wq_w, wq_b, 0.125f, qhi, qlo);
    gemm_proj<<<grid_proj, 256, G_SM_TOTAL>>>(k, wk_w, wk_b, 1.0f, khi, klo);
    gemm_projT<<<grid_proj, 256, G_SM_TOTAL>>>(v, wv_w, wv_b, vthi, vtlo);

    dim3 grid_attn(L_ / 64, H_, B_);             // (32, 8, 4)
    attn_fused<<<grid_attn, 128, F_TOTAL>>>(qhi, qlo, khi, klo, vthi, vtlo,
                                            mask, attn_ptr, ctx, invl);

    out_scale<<<1024, 256, G_SM_TOTAL>>>(ctx, wo_w, wo_b, out,
                                         (float4*)attn_ptr, invl);
}

// round 13
// speedup vs baseline: 1.6212x; 1.0585x over previous
#include <cuda_runtime.h>
#include <cuda_bf16.h>
#include <cstdint>
#include <cstddef>

#define B_  4
#define L_  2048
#define D_  512
#define H_  8
#define DH_ 64

typedef __nv_bfloat16 bf16;

#define PROJ_E ((size_t)B_ * H_ * L_ * DH_)   // 4194304
#define W_E    ((size_t)D_ * D_)              // 262144

// pre-split inputs / weights
__device__ bf16  g_xqhi[PROJ_E]; __device__ bf16 g_xqlo[PROJ_E];
__device__ bf16  g_xkhi[PROJ_E]; __device__ bf16 g_xklo[PROJ_E];
__device__ bf16  g_xvhi[PROJ_E]; __device__ bf16 g_xvlo[PROJ_E];
__device__ bf16  g_wqhi[W_E]; __device__ bf16 g_wqlo[W_E];
__device__ bf16  g_wkhi[W_E]; __device__ bf16 g_wklo[W_E];
__device__ bf16  g_wvhi[W_E]; __device__ bf16 g_wvlo[W_E];
__device__ bf16  g_wohi[W_E]; __device__ bf16 g_wolo[W_E];
// projected tensors
__device__ bf16  g_qhi[PROJ_E];  __device__ bf16 g_qlo[PROJ_E];
__device__ bf16  g_khi[PROJ_E];  __device__ bf16 g_klo[PROJ_E];
__device__ bf16  g_vthi[PROJ_E]; __device__ bf16 g_vtlo[PROJ_E];
__device__ bf16  g_ctxhi[PROJ_E]; __device__ bf16 g_ctxlo[PROJ_E];
__device__ float g_invl[(size_t)B_ * H_ * L_];
__device__ float g_attn_fb[(size_t)B_ * H_ * L_ * L_];

__device__ __forceinline__ uint32_t smem_u32(const void* p) {
    uint32_t a;
    asm("{ .reg .u64 t; cvta.to.shared.u64 t, %1; cvt.u32.u64 %0, t; }"
        : "=r"(a) : "l"(p));
    return a;
}

#define LDSM4(R0, R1, R2, R3, A) \
    asm volatile("ldmatrix.sync.aligned.m8n8.x4.shared.b16 {%0,%1,%2,%3}, [%4];" \
                 : "=r"(R0), "=r"(R1), "=r"(R2), "=r"(R3) : "r"(A))

#define MMA4(D, A0, A1, A2, A3, Bb0, Bb1) \
    asm volatile("mma.sync.aligned.m16n8k16.row.col.f32.bf16.bf16.f32 " \
                 "{%0,%1,%2,%3}, {%4,%5,%6,%7}, {%8,%9}, {%0,%1,%2,%3};" \
                 : "+f"((D)[0]), "+f"((D)[1]), "+f"((D)[2]), "+f"((D)[3]) \
                 : "r"(A0), "r"(A1), "r"(A2), "r"(A3), "r"(Bb0), "r"(Bb1))

#define CPA(dst, src) \
    asm volatile("cp.async.ca.shared.global [%0], [%1], 16;" \
                 :: "r"((uint32_t)(dst)), "l"(src) : "memory")
#define CPC()  asm volatile("cp.async.commit_group;" ::: "memory")
#define CPW0() asm volatile("cp.async.wait_group 0;" ::: "memory")

__device__ __forceinline__ uint32_t pack2(bf16 a, bf16 b) {
    return (uint32_t)__bfloat16_as_ushort(a) |
           ((uint32_t)__bfloat16_as_ushort(b) << 16);
}

// ---------------- pre-split converters ------------------------------------
__global__ void __launch_bounds__(256, 4)
convertX(const float* __restrict__ q, const float* __restrict__ k,
         const float* __restrict__ v,
         bf16* qh, bf16* ql, bf16* kh, bf16* kl, bf16* vh, bf16* vl)
{
    const float* src = blockIdx.y == 0 ? q : (blockIdx.y == 1 ? k : v);
    bf16* dh = blockIdx.y == 0 ? qh : (blockIdx.y == 1 ? kh : vh);
    bf16* dl = blockIdx.y == 0 ? ql : (blockIdx.y == 1 ? kl : vl);
    size_t i = ((size_t)blockIdx.x * 256 + threadIdx.x) * 4;
    float4 x = *(const float4*)(src + i);
    bf16 h0 = __float2bfloat16(x.x), h1 = __float2bfloat16(x.y);
    bf16 h2 = __float2bfloat16(x.z), h3 = __float2bfloat16(x.w);
    *(uint2*)(dh + i) = make_uint2(pack2(h0, h1), pack2(h2, h3));
    *(uint2*)(dl + i) = make_uint2(
        pack2(__float2bfloat16(x.x - __bfloat162float(h0)),
              __float2bfloat16(x.y - __bfloat162float(h1))),
        pack2(__float2bfloat16(x.z - __bfloat162float(h2)),
              __float2bfloat16(x.w - __bfloat162float(h3))));
}

__global__ void __launch_bounds__(256, 4)
convertW(const float* __restrict__ wq, const float* __restrict__ wk,
         const float* __restrict__ wv, const float* __restrict__ wo,
         bf16* qh, bf16* ql, bf16* kh, bf16* kl,
         bf16* vh, bf16* vl, bf16* oh, bf16* ol)
{
    int y = blockIdx.y;
    const float* src = y == 0 ? wq : (y == 1 ? wk : (y == 2 ? wv : wo));
    bf16* dh = y == 0 ? qh : (y == 1 ? kh : (y == 2 ? vh : oh));
    bf16* dl = y == 0 ? ql : (y == 1 ? kl : (y == 2 ? vl : ol));
    size_t i = ((size_t)blockIdx.x * 256 + threadIdx.x) * 4;
    float4 x = *(const float4*)(src + i);
    bf16 h0 = __float2bfloat16(x.x), h1 = __float2bfloat16(x.y);
    bf16 h2 = __float2bfloat16(x.z), h3 = __float2bfloat16(x.w);
    *(uint2*)(dh + i) = make_uint2(pack2(h0, h1), pack2(h2, h3));
    *(uint2*)(dl + i) = make_uint2(
        pack2(__float2bfloat16(x.x - __bfloat162float(h0)),
              __float2bfloat16(x.y - __bfloat162float(h1))),
        pack2(__float2bfloat16(x.z - __bfloat162float(h2)),
              __float2bfloat16(x.w - __bfloat162float(h3))));
}

// =====================================================================
// bf16 GEMM: C[r,c] = (sum_k X[r,k]*W[c,k] + bias[c]) * oscale
// 128 threads, tile m64 x n64, K-chunks of 64, cp.async double-buffer.
// MODE 0: fp32 flat out; MODE 1: bf16 hi/lo [B,H,L,64]; MODE 2: [B,H,64,L]
// smem: stage(s)=s*36864: AHI+0 ALO+9216 BHI+18432 BLO+27648; total 73728
// =====================================================================
#define GPK 144
#define GB_TOTAL 73728
#define TS_PT 144

template <int MODE>
__device__ __forceinline__ void
gemm_bf16_body(const bf16* __restrict__ Xhi, const bf16* __restrict__ Xlo,
               const bf16* __restrict__ Whi, const bf16* __restrict__ Wlo,
               const float* __restrict__ bias, float oscale,
               float* __restrict__ out32, bf16* __restrict__ oHi,
               bf16* __restrict__ oLo, int n0, int mb,
               char* sm_, uint32_t sb)
{
    const int t = threadIdx.x, lane = t & 31, w = t >> 5, qq = lane & 3;
    const int m0 = w * 16;
    const int rB = (lane & 7) + ((lane & 16) >> 1);
    const int cB = (lane >> 3) & 1;
    const int rA = lane & 15, cA = lane >> 4;

#define GPRE(kc_, par_)                                                       \
    do {                                                                      \
        uint32_t bas = sb + (par_) * 36864;                                   \
        _Pragma("unroll")                                                     \
        for (int e = 0; e < 4; e++) {                                         \
            int i = t + e * 128;                                              \
            int row = i >> 3, c16 = i & 7;                                    \
            CPA(bas + row * GPK + c16 * 16,                                   \
                Xhi + (size_t)(mb + row) * D_ + (kc_) + c16 * 8);             \
            CPA(bas + 9216 + row * GPK + c16 * 16,                            \
                Xlo + (size_t)(mb + row) * D_ + (kc_) + c16 * 8);             \
            CPA(bas + 18432 + row * GPK + c16 * 16,                           \
                Whi + (size_t)(n0 + row) * D_ + (kc_) + c16 * 8);             \
            CPA(bas + 27648 + row * GPK + c16 * 16,                           \
                Wlo + (size_t)(n0 + row) * D_ + (kc_) + c16 * 8);             \
        }                                                                     \
        CPC();                                                                \
    } while (0)

    GPRE(0, 0);

    float S[8][4];
#pragma unroll
    for (int i = 0; i < 8; i++)
#pragma unroll
        for (int j = 0; j < 4; j++) S[i][j] = 0.f;

#pragma unroll 1
    for (int kc6 = 0; kc6 < 8; kc6++) {
        const int par = kc6 & 1;
        CPW0();
        __syncthreads();
        if (kc6 < 7) GPRE((kc6 + 1) * 64, par ^ 1);

        const uint32_t ab = sb + par * 36864;
        uint32_t ah[4][4], al[4][4];
#pragma unroll
        for (int ks = 0; ks < 4; ks++) {
            LDSM4(ah[ks][0], ah[ks][1], ah[ks][2], ah[ks][3],
                  ab + (m0 + rA) * GPK + ks * 32 + cA * 16);
            LDSM4(al[ks][0], al[ks][1], al[ks][2], al[ks][3],
                  ab + 9216 + (m0 + rA) * GPK + ks * 32 + cA * 16);
        }
#pragma unroll
        for (int ks = 0; ks < 4; ks++) {
            uint32_t bh[4][4];
#pragma unroll
            for (int n2 = 0; n2 < 4; n2++)
                LDSM4(bh[n2][0], bh[n2][1], bh[n2][2], bh[n2][3],
                      ab + 18432 + (n2 * 16 + rB) * GPK + ks * 32 + cB * 16);
#pragma unroll
            for (int n2 = 0; n2 < 4; n2++) {
                MMA4(S[2 * n2],     ah[ks][0], ah[ks][1], ah[ks][2], ah[ks][3],
                     bh[n2][0], bh[n2][1]);
                MMA4(S[2 * n2 + 1], ah[ks][0], ah[ks][1], ah[ks][2], ah[ks][3],
                     bh[n2][2], bh[n2][3]);
            }
#pragma unroll
            for (int n2 = 0; n2 < 4; n2++) {
                MMA4(S[2 * n2],     al[ks][0], al[ks][1], al[ks][2], al[ks][3],
                     bh[n2][0], bh[n2][1]);
                MMA4(S[2 * n2 + 1], al[ks][0], al[ks][1], al[ks][2], al[ks][3],
                     bh[n2][2], bh[n2][3]);
            }
#pragma unroll
            for (int n2 = 0; n2 < 4; n2++) {
                uint32_t c0, c1, c2, c3;
                LDSM4(c0, c1, c2, c3,
                      ab + 27648 + (n2 * 16 + rB) * GPK + ks * 32 + cB * 16);
                MMA4(S[2 * n2],     ah[ks][0], ah[ks][1], ah[ks][2], ah[ks][3],
                     c0, c1);
                MMA4(S[2 * n2 + 1], ah[ks][0], ah[ks][1], ah[ks][2], ah[ks][3],
                     c2, c3);
            }
        }
        __syncthreads();
    }
#undef GPRE

    const int rA_ = mb + m0 + (lane >> 2);
    const int rB_ = rA_ + 8;

    if (MODE == 2) {
        // stage transposed bf16 hi/lo in smem (pitch 144), coalesced write
        const int mA = m0 + (lane >> 2), mB = mA + 8;
#pragma unroll
        for (int nt = 0; nt < 8; nt++) {
            int c = nt * 8 + qq * 2;
            float bs0 = bias[n0 + c], bs1 = bias[n0 + c + 1];
            float v00 = S[nt][0] + bs0, v01 = S[nt][1] + bs1;
            float v10 = S[nt][2] + bs0, v11 = S[nt][3] + bs1;
            bf16 h;
            h = __float2bfloat16(v00);
            *(bf16*)(sm_ + c * TS_PT + mA * 2) = h;
            *(bf16*)(sm_ + 18432 + c * TS_PT + mA * 2) =
                __float2bfloat16(v00 - __bfloat162float(h));
            h = __float2bfloat16(v01);
            *(bf16*)(sm_ + (c + 1) * TS_PT + mA * 2) = h;
            *(bf16*)(sm_ + 18432 + (c + 1) * TS_PT + mA * 2) =
                __float2bfloat16(v01 - __bfloat162float(h));
            h = __float2bfloat16(v10);
            *(bf16*)(sm_ + c * TS_PT + mB * 2) = h;
            *(bf16*)(sm_ + 18432 + c * TS_PT + mB * 2) =
                __float2bfloat16(v10 - __bfloat162float(h));
            h = __float2bfloat16(v11);
            *(bf16*)(sm_ + (c + 1) * TS_PT + mB * 2) = h;
            *(bf16*)(sm_ + 18432 + (c + 1) * TS_PT + mB * 2) =
                __float2bfloat16(v11 - __bfloat162float(h));
        }
        __syncthreads();
        const int bA = mb >> 11, lA0 = mb & 2047;
        const int cl = t >> 1, half = t & 1;     // 64 cols x 2 halves
        const int hh = (n0 + cl) >> 6, dh = (n0 + cl) & 63;
        size_t gbase = ((size_t)((bA * H_ + hh) * DH_) + dh) * L_ + lA0 + half * 32;
        const char* srcH = sm_ + cl * TS_PT + half * 64;
        const char* srcL = sm_ + 18432 + cl * TS_PT + half * 64;
#pragma unroll
        for (int e = 0; e < 4; e++) {
            *(uint4*)(oHi + gbase + e * 8) = *(const uint4*)(srcH + e * 16);
            *(uint4*)(oLo + gbase + e * 8) = *(const uint4*)(srcL + e * 16);
        }
        return;
    }

#pragma unroll
    for (int nt = 0; nt < 8; nt++) {
        int c = n0 + nt * 8 + qq * 2;
        float bs0 = bias[c], bs1 = bias[c + 1];
        float v00 = (S[nt][0] + bs0) * oscale, v01 = (S[nt][1] + bs1) * oscale;
        float v10 = (S[nt][2] + bs0) * oscale, v11 = (S[nt][3] + bs1) * oscale;
        if (MODE == 0) {
            *(float2*)(out32 + (size_t)rA_ * D_ + c) = make_float2(v00, v01);
            *(float2*)(out32 + (size_t)rB_ * D_ + c) = make_float2(v10, v11);
        } else {
            int hh = c >> 6, dh = c & 63;
            int bA = rA_ >> 11, lA = rA_ & 2047;
            int bB = rB_ >> 11, lB = rB_ & 2047;
            size_t iA = ((size_t)((bA * H_ + hh) * L_) + lA) * DH_ + dh;
            size_t iB = ((size_t)((bB * H_ + hh) * L_) + lB) * DH_ + dh;
            bf16 h0 = __float2bfloat16(v00), h1 = __float2bfloat16(v01);
            *(uint32_t*)(oHi + iA) = pack2(h0, h1);
            *(uint32_t*)(oLo + iA) = pack2(
                __float2bfloat16(v00 - __bfloat162float(h0)),
                __float2bfloat16(v01 - __bfloat162float(h1)));
            h0 = __float2bfloat16(v10); h1 = __float2bfloat16(v11);
            *(uint32_t*)(oHi + iB) = pack2(h0, h1);
            *(uint32_t*)(oLo + iB) = pack2(
                __float2bfloat16(v10 - __bfloat162float(h0)),
                __float2bfloat16(v11 - __bfloat162float(h1)));
        }
    }
}

__global__ void __launch_bounds__(128, 3)
gemm_b1(const bf16* Xhi, const bf16* Xlo, const bf16* Whi, const bf16* Wlo,
        const float* bias, float oscale, bf16* oHi, bf16* oLo)
{
    extern __shared__ char sm_[];
    gemm_bf16_body<1>(Xhi, Xlo, Whi, Wlo, bias, oscale, nullptr, oHi, oLo,
                      blockIdx.x * 64, blockIdx.y * 64, sm_, smem_u32(sm_));
}

__global__ void __launch_bounds__(128, 3)
gemm_b2(const bf16* Xhi, const bf16* Xlo, const bf16* Whi, const bf16* Wlo,
        const float* bias, bf16* oHi, bf16* oLo)
{
    extern __shared__ char sm_[];
    gemm_bf16_body<2>(Xhi, Xlo, Whi, Wlo, bias, 1.f, nullptr, oHi, oLo,
                      blockIdx.x * 64, blockIdx.y * 64, sm_, smem_u32(sm_));
}

__global__ void __launch_bounds__(128, 3)
gemm_b0(const bf16* Xhi, const bf16* Xlo, const bf16* Whi, const bf16* Wlo,
        const float* bias, float* out32)
{
    extern __shared__ char sm_[];
    gemm_bf16_body<0>(Xhi, Xlo, Whi, Wlo, bias, 1.f, out32, nullptr, nullptr,
                      blockIdx.x * 64, blockIdx.y * 64, sm_, smem_u32(sm_));
}

// =====================================================================
// Fused attention (R11 core; ctx now written as bf16 hi/lo)
// =====================================================================
#define PK 144
#define F_M0   0
#define F_M1   256
#define F_KHI0 1024
#define F_KHI1 (F_KHI0 + 18432)
#define F_VHI0 (F_KHI1 + 18432)
#define F_VHI1 (F_VHI0 + 18432)
#define F_TOTAL (F_VHI1 + 18432)   // 74752

__global__ void __launch_bounds__(128, 2)
attn_fused(const bf16* __restrict__ qhi, const bf16* __restrict__ qlo,
           const bf16* __restrict__ khi, const bf16* __restrict__ klo,
           const bf16* __restrict__ vthi, const bf16* __restrict__ vtlo,
           const int*  __restrict__ mask,
           float* __restrict__ attn, bf16* __restrict__ ctxhi,
           bf16* __restrict__ ctxlo, float* __restrict__ invl_out)
{
    extern __shared__ char sm_[];
    const uint32_t sb = smem_u32(sm_);
    const int t = threadIdx.x, lane = t & 31, w = t >> 5, qq = lane & 3;
    const int q0 = blockIdx.x * 64, h = blockIdx.y, b = blockIdx.z;
    const size_t hb = (size_t)(b * H_ + h) * L_;
    const size_t headoff = hb * DH_;
    const int m0 = w * 16;
    const int rB = (lane & 7) + ((lane & 16) >> 1);
    const int cB = (lane >> 3) & 1;
    const int rA = lane & 15, cA = lane >> 4;
    const int r0 = m0 + (lane >> 2);

#pragma unroll
    for (int e = 0; e < 4; e++) {
        int i = t + e * 128;
        int row = i >> 3, c16 = i & 7;
        *(uint4*)(sm_ + F_KHI0 + row * PK + c16 * 16) =
            *(const uint4*)(qhi + headoff + (size_t)(q0 + row) * DH_ + c16 * 8);
        *(uint4*)(sm_ + F_KHI0 + 9216 + row * PK + c16 * 16) =
            *(const uint4*)(qlo + headoff + (size_t)(q0 + row) * DH_ + c16 * 8);
    }
    __syncthreads();
    uint32_t qh[4][4], ql[4][4];
#pragma unroll
    for (int ks = 0; ks < 4; ks++) {
        LDSM4(qh[ks][0], qh[ks][1], qh[ks][2], qh[ks][3],
              sb + F_KHI0 + (m0 + rA) * PK + ks * 32 + cA * 16);
        LDSM4(ql[ks][0], ql[ks][1], ql[ks][2], ql[ks][3],
              sb + F_KHI0 + 9216 + (m0 + rA) * PK + ks * 32 + cA * 16);
    }
    __syncthreads();

#define PREFETCH(kt_, par_)                                                   \
    do {                                                                      \
        uint32_t kh_ = sb + ((par_) ? F_KHI1 : F_KHI0);                       \
        uint32_t vh_ = sb + ((par_) ? F_VHI1 : F_VHI0);                       \
        const bf16* kg = khi + headoff + (size_t)((kt_) * 64) * DH_;          \
        const bf16* lg = klo + headoff + (size_t)((kt_) * 64) * DH_;          \
        const bf16* vg = vthi + headoff + (kt_) * 64;                         \
        const bf16* wg = vtlo + headoff + (kt_) * 64;                         \
        _Pragma("unroll")                                                     \
        for (int e = 0; e < 4; e++) {                                         \
            int i = t + e * 128;                                              \
            int row = i >> 3, c16 = i & 7;                                    \
            CPA(kh_ + row * PK + c16 * 16, kg + (size_t)row * DH_ + c16 * 8); \
            CPA(kh_ + 9216 + row * PK + c16 * 16,                             \
                lg + (size_t)row * DH_ + c16 * 8);                            \
            CPA(vh_ + row * PK + c16 * 16, vg + (size_t)row * L_ + c16 * 8);  \
            CPA(vh_ + 9216 + row * PK + c16 * 16,                             \
                wg + (size_t)row * L_ + c16 * 8);                             \
        }                                                                     \
        if (t < 16)                                                           \
            CPA(sb + ((par_) ? F_M1 : F_M0) + t * 16,                         \
                mask + b * L_ + (kt_) * 64 + t * 4);                          \
        CPC();                                                                \
    } while (0)

    PREFETCH(0, 0);

    float O[8][4];
#pragma unroll
    for (int i = 0; i < 8; i++)
#pragma unroll
        for (int j = 0; j < 4; j++) O[i][j] = 0.f;
    float lrunA = 0.f, lrunB = 0.f;

#pragma unroll 1
    for (int kt6 = 0; kt6 < 32; kt6++) {
        const int par = kt6 & 1;
        CPW0();
        __syncthreads();
        if (kt6 < 31) PREFETCH(kt6 + 1, par ^ 1);

        const uint32_t khb = sb + (par ? F_KHI1 : F_KHI0);
        const uint32_t vhb = sb + (par ? F_VHI1 : F_VHI0);
        const int* mi = (const int*)(sm_ + (par ? F_M1 : F_M0));

        float S[8][4];
#pragma unroll
        for (int i = 0; i < 8; i++)
#pragma unroll
            for (int j = 0; j < 4; j++) S[i][j] = 0.f;

#pragma unroll
        for (int ks = 0; ks < 4; ks++) {
            uint32_t bh[4][4];
#pragma unroll
            for (int n2 = 0; n2 < 4; n2++)
                LDSM4(bh[n2][0], bh[n2][1], bh[n2][2], bh[n2][3],
                      khb + (n2 * 16 + rB) * PK + ks * 32 + cB * 16);
#pragma unroll
            for (int n2 = 0; n2 < 4; n2++) {
                MMA4(S[2 * n2],     qh[ks][0], qh[ks][1], qh[ks][2], qh[ks][3],
                     bh[n2][0], bh[n2][1]);
                MMA4(S[2 * n2 + 1], qh[ks][0], qh[ks][1], qh[ks][2], qh[ks][3],
                     bh[n2][2], bh[n2][3]);
            }
#pragma unroll
            for (int n2 = 0; n2 < 4; n2++) {
                MMA4(S[2 * n2],     ql[ks][0], ql[ks][1], ql[ks][2], ql[ks][3],
                     bh[n2][0], bh[n2][1]);
                MMA4(S[2 * n2 + 1], ql[ks][0], ql[ks][1], ql[ks][2], ql[ks][3],
                     bh[n2][2], bh[n2][3]);
            }
#pragma unroll
            for (int n2 = 0; n2 < 4; n2++) {
                uint32_t c0, c1, c2, c3;
                LDSM4(c0, c1, c2, c3,
                      khb + 9216 + (n2 * 16 + rB) * PK + ks * 32 + cB * 16);
                MMA4(S[2 * n2],     qh[ks][0], qh[ks][1], qh[ks][2], qh[ks][3],
                     c0, c1);
                MMA4(S[2 * n2 + 1], qh[ks][0], qh[ks][1], qh[ks][2], qh[ks][3],
                     c2, c3);
            }
        }

        float* arow0 = attn + (hb + q0 + r0) * (size_t)L_ + kt6 * 64;
        float* arow1 = arow0 + 8 * L_;
#pragma unroll
        for (int nt = 0; nt < 8; nt++) {
            int c0 = nt * 8 + qq * 2;
            bool k0m = mi[c0] != 0, k1m = mi[c0 + 1] != 0;
            float e0 = k0m ? 0.f : __expf(S[nt][0]);
            float e1 = k1m ? 0.f : __expf(S[nt][1]);
            float e2 = k0m ? 0.f : __expf(S[nt][2]);
            float e3 = k1m ? 0.f : __expf(S[nt][3]);
            lrunA += e0 + e1; lrunB += e2 + e3;
            S[nt][0] = e0; S[nt][1] = e1; S[nt][2] = e2; S[nt][3] = e3;
            *(float2*)(arow0 + c0) = make_float2(e0, e1);
            *(float2*)(arow1 + c0) = make_float2(e2, e3);
        }

#pragma unroll
        for (int ks = 0; ks < 4; ks++) {
            bf16 h00 = __float2bfloat16(S[2 * ks][0]);
            bf16 h01 = __float2bfloat16(S[2 * ks][1]);
            bf16 h02 = __float2bfloat16(S[2 * ks][2]);
            bf16 h03 = __float2bfloat16(S[2 * ks][3]);
            bf16 h10 = __float2bfloat16(S[2 * ks + 1][0]);
            bf16 h11 = __float2bfloat16(S[2 * ks + 1][1]);
            bf16 h12 = __float2bfloat16(S[2 * ks + 1][2]);
            bf16 h13 = __float2bfloat16(S[2 * ks + 1][3]);
            uint32_t a0h = pack2(h00, h01), a1h = pack2(h02, h03);
            uint32_t a2h = pack2(h10, h11), a3h = pack2(h12, h13);
            uint32_t a0l = pack2(
                __float2bfloat16(S[2 * ks][0] - __bfloat162float(h00)),
                __float2bfloat16(S[2 * ks][1] - __bfloat162float(h01)));
            uint32_t a1l = pack2(
                __float2bfloat16(S[2 * ks][2] - __bfloat162float(h02)),
                __float2bfloat16(S[2 * ks][3] - __bfloat162float(h03)));
            uint32_t a2l = pack2(
                __float2bfloat16(S[2 * ks + 1][0] - __bfloat162float(h10)),
                __float2bfloat16(S[2 * ks + 1][1] - __bfloat162float(h11)));
            uint32_t a3l = pack2(
                __float2bfloat16(S[2 * ks + 1][2] - __bfloat162float(h12)),
                __float2bfloat16(S[2 * ks + 1][3] - __bfloat162float(h13)));
            uint32_t vh[4][4];
#pragma unroll
            for (int n2 = 0; n2 < 4; n2++)
                LDSM4(vh[n2][0], vh[n2][1], vh[n2][2], vh[n2][3],
                      vhb + (n2 * 16 + rB) * PK + ks * 32 + cB * 16);
#pragma unroll
            for (int n2 = 0; n2 < 4; n2++) {
                MMA4(O[2 * n2],     a0h, a1h, a2h, a3h, vh[n2][0], vh[n2][1]);
                MMA4(O[2 * n2 + 1], a0h, a1h, a2h, a3h, vh[n2][2], vh[n2][3]);
            }
#pragma unroll
            for (int n2 = 0; n2 < 4; n2++) {
                MMA4(O[2 * n2],     a0l, a1l, a2l, a3l, vh[n2][0], vh[n2][1]);
                MMA4(O[2 * n2 + 1], a0l, a1l, a2l, a3l, vh[n2][2], vh[n2][3]);
            }
#pragma unroll
            for (int n2 = 0; n2 < 4; n2++) {
                uint32_t c0, c1, c2, c3;
                LDSM4(c0, c1, c2, c3,
                      vhb + 9216 + (n2 * 16 + rB) * PK + ks * 32 + cB * 16);
                MMA4(O[2 * n2],     a0h, a1h, a2h, a3h, c0, c1);
                MMA4(O[2 * n2 + 1], a0h, a1h, a2h, a3h, c2, c3);
            }
        }
        __syncthreads();
    }
#undef PREFETCH

    lrunA += __shfl_xor_sync(0xffffffffu, lrunA, 1);
    lrunA += __shfl_xor_sync(0xffffffffu, lrunA, 2);
    lrunB += __shfl_xor_sync(0xffffffffu, lrunB, 1);
    lrunB += __shfl_xor_sync(0xffffffffu, lrunB, 2);
    float ilA = 1.f / lrunA, ilB = 1.f / lrunB;
    if (qq == 0) {
        invl_out[hb + q0 + r0]     = ilA;
        invl_out[hb + q0 + r0 + 8] = ilB;
    }
    int rg = q0 + r0;
#pragma unroll
    for (int nt = 0; nt < 8; nt++) {
        int d = nt * 8 + qq * 2;
        size_t iA = ((size_t)b * L_ + rg) * D_ + h * 64 + d;
        size_t iB = ((size_t)b * L_ + rg + 8) * D_ + h * 64 + d;
        float v0 = O[nt][0] * ilA, v1 = O[nt][1] * ilA;
        bf16 h0 = __float2bfloat16(v0), h1 = __float2bfloat16(v1);
        *(uint32_t*)(ctxhi + iA) = pack2(h0, h1);
        *(uint32_t*)(ctxlo + iA) = pack2(
            __float2bfloat16(v0 - __bfloat162float(h0)),
            __float2bfloat16(v1 - __bfloat162float(h1)));
        v0 = O[nt][2] * ilB; v1 = O[nt][3] * ilB;
        h0 = __float2bfloat16(v0); h1 = __float2bfloat16(v1);
        *(uint32_t*)(ctxhi + iB) = pack2(h0, h1);
        *(uint32_t*)(ctxlo + iB) = pack2(
            __float2bfloat16(v0 - __bfloat162float(h0)),
            __float2bfloat16(v1 - __bfloat162float(h1)));
    }
}

// ---------------- streaming normalize of the attn strip --------------------
__global__ void __launch_bounds__(512, 2)
scale_attn(float4* __restrict__ a, const float* __restrict__ invl)
{
    const size_t n4 = (size_t)B_ * H_ * L_ * L_ / 4;
    size_t i = (size_t)blockIdx.x * blockDim.x + threadIdx.x;
    const size_t stride = (size_t)gridDim.x * blockDim.x;
    for (; i < n4; i += stride) {
        float s = __ldg(invl + (i >> 9));
        float4 v = a[i];
        v.x *= s; v.y *= s; v.z *= s; v.w *= s;
        a[i] = v;
    }
}

extern "C" void kernel_launch(void* const* d_in, const int* in_sizes, int n_in,
                              void* d_out, int out_size)
{
    const float* q    = (const float*)d_in[0];
    const float* k    = (const float*)d_in[1];
    const float* v    = (const float*)d_in[2];
    const int*   mask = (const int*)  d_in[3];
    const float* wq_w = (const float*)d_in[4];
    const float* wq_b = (const float*)d_in[5];
    const float* wk_w = (const float*)d_in[6];
    const float* wk_b = (const float*)d_in[7];
    const float* wv_w = (const float*)d_in[8];
    const float* wv_b = (const float*)d_in[9];
    const float* wo_w = (const float*)d_in[10];
    const float* wo_b = (const float*)d_in[11];

    float* out = (float*)d_out;
    const long long OUT_E  = (long long)B_ * L_ * D_;
    const long long ATTN_E = (long long)B_ * H_ * L_ * L_;

    float* attn_ptr;
    if ((long long)out_size >= OUT_E + ATTN_E) {
        attn_ptr = out + OUT_E;
    } else {
        void* p = nullptr;
        cudaGetSymbolAddress(&p, g_attn_fb);
        attn_ptr = (float*)p;
    }

#define SYM(T, name, var) T* var; { void* p; cudaGetSymbolAddress(&p, name); var = (T*)p; }
    SYM(bf16, g_xqhi, xqh) SYM(bf16, g_xqlo, xql)
    SYM(bf16, g_xkhi, xkh) SYM(bf16, g_xklo, xkl)
    SYM(bf16, g_xvhi, xvh) SYM(bf16, g_xvlo, xvl)
    SYM(bf16, g_wqhi, wqh) SYM(bf16, g_wqlo, wql)
    SYM(bf16, g_wkhi, wkh) SYM(bf16, g_wklo, wkl)
    SYM(bf16, g_wvhi, wvh) SYM(bf16, g_wvlo, wvl)
    SYM(bf16, g_wohi, woh) SYM(bf16, g_wolo, wol)
    SYM(bf16, g_qhi, qhi)  SYM(bf16, g_qlo, qlo)
    SYM(bf16, g_khi, khi)  SYM(bf16, g_klo, klo)
    SYM(bf16, g_vthi, vthi) SYM(bf16, g_vtlo, vtlo)
    SYM(bf16, g_ctxhi, ctxhi) SYM(bf16, g_ctxlo, ctxlo)
    SYM(float, g_invl, invl)
#undef SYM

    cudaFuncSetAttribute(gemm_b0,
        cudaFuncAttributeMaxDynamicSharedMemorySize, GB_TOTAL);
    cudaFuncSetAttribute(gemm_b1,
        cudaFuncAttributeMaxDynamicSharedMemorySize, GB_TOTAL);
    cudaFuncSetAttribute(gemm_b2,
        cudaFuncAttributeMaxDynamicSharedMemorySize, GB_TOTAL);
    cudaFuncSetAttribute(attn_fused,
        cudaFuncAttributeMaxDynamicSharedMemorySize, F_TOTAL);

    // pre-split inputs + weights
    convertX<<<dim3(PROJ_E / 1024, 3), 256>>>(q, k, v, xqh, xql, xkh, xkl,
                                              xvh, xvl);
    convertW<<<dim3(W_E / 1024, 4), 256>>>(wq_w, wk_w, wv_w, wo_w,
                                           wqh, wql, wkh, wkl,
                                           wvh, wvl, woh, wol);

    dim3 gg(D_ / 64, (B_ * L_) / 64);            // (8, 128)
    gemm_b1<<<gg, 128, GB_TOTAL>>>(xqh, xql, wqh, wql, wq_b, 0.125f, qhi, qlo);
    gemm_b1<<<gg, 128, GB_TOTAL>>>(xkh, xkl, wkh, wkl, wk_b, 1.0f, khi, klo);
    gemm_b2<<<gg, 128, GB_TOTAL>>>(xvh, xvl, wvh, wvl, wv_b, vthi, vtlo);

    dim3 grid_attn(L_ / 64, H_, B_);             // (32, 8, 4)
    attn_fused<<<grid_attn, 128, F_TOTAL>>>(qhi, qlo, khi, klo, vthi, vtlo,
                                            mask, attn_ptr, ctxhi, ctxlo, invl);

    scale_attn<<<16384, 512>>>((float4*)attn_ptr, invl);

    gemm_b0<<<gg, 128, GB_TOTAL>>>(ctxhi, ctxlo, woh, wol, wo_b, out);
}